// round 4
// baseline (speedup 1.0000x reference)
#include <cuda_runtime.h>
#include <math.h>

// Problem dims (fixed by the reference)
#define BB 64
#define TD 128
#define TE 256
#define DX 1024
#define HH 1024

// ---------------- persistent state (static device globals; no allocations) ---------
__device__ float g_h[BB * HH];        // GRU hidden state
__device__ float g_ifeed[BB * HH];    // previous attention output (input feeding)
__device__ float g_feed[BB * HH];     // tanh(ifeed @ Wfeed + bfeed)
__device__ float g_gx[BB * 3 * HH];   // i_cat @ Wx + bxi
__device__ float g_gh[BB * 3 * HH];   // h @ Wh + bhr
__device__ float g_value[BB * HH];    // attention context vector

// ---------------- init: h = h_enc, i_feed = 0 --------------------------------------
__global__ void init64(const float* __restrict__ h_enc) {
    int idx = blockIdx.x * blockDim.x + threadIdx.x;
    if (idx < BB * HH) {
        g_h[idx] = h_enc[idx];
        g_ifeed[idx] = 0.0f;
    }
}

// ---------------- generic skinny GEMM: C[64,N] = A[64,K] @ W[K,N] + bias ------------
// Block computes a 64x8 output tile. 128 threads; thread (mg,nn) owns 4 m-rows x 1 col.
// aSel: 0 = g_ifeed (plain, lda=K)
//       1 = concat [g_feed | Aext] split at 1024, Aext row stride a1stride
//       2 = g_h (plain, lda=K)
//       3 = concat [g_value | g_h] split at 1024 (a1stride must be HH)
// outSel: 0 -> g_feed (ldc=HH), 1 -> g_gx (ldc=3H), 2 -> g_gh (ldc=3H),
//         3 -> Cext (ldc=TD*HH) AND g_ifeed (ldc=HH)   [dual write for h_att]
// act: 0 none, 1 tanh
__global__ __launch_bounds__(128)
void gemm64(const float* __restrict__ Aext,
            const float* __restrict__ W,
            const float* __restrict__ bias,
            float* __restrict__ Cext,
            int K, int N, int a1stride, int aSel, int outSel, int act)
{
    __shared__ __align__(16) float sA[16][68];   // [k][m], padded, float4-readable
    __shared__ float sW[16][8];

    const int tid = threadIdx.x;
    const int n0  = blockIdx.x * 8;
    const int mg  = tid & 15;     // 0..15 -> m0 = mg*4
    const int nn  = tid >> 4;     // 0..7

    const float* A0 = (aSel == 0) ? g_ifeed
                    : (aSel == 1) ? g_feed
                    : (aSel == 2) ? g_h
                    :               g_value;
    const float* A1 = (aSel == 1) ? Aext : g_h;   // used only for aSel 1 / 3

    float4 acc = make_float4(0.f, 0.f, 0.f, 0.f);

    const int ntiles = K >> 4;
    for (int kt = 0; kt < ntiles; ++kt) {
        const int k0 = kt << 4;
        // load A tile (64 x 16) transposed into smem
        #pragma unroll
        for (int r = 0; r < 8; ++r) {
            int idx = (r << 7) + tid;       // 0..1023
            int m = idx >> 4;
            int c = idx & 15;
            int k = k0 + c;
            float v;
            if (aSel == 0 || aSel == 2) {
                v = A0[m * K + k];
            } else {
                v = (k < HH) ? A0[m * HH + k]
                             : A1[m * a1stride + (k - HH)];
            }
            sA[c][m] = v;
        }
        // load W tile (16 x 8)
        {
            int r = tid >> 3;   // 0..15
            int cn = tid & 7;   // 0..7
            sW[r][cn] = W[(size_t)(k0 + r) * N + (n0 + cn)];
        }
        __syncthreads();
        #pragma unroll
        for (int kk = 0; kk < 16; ++kk) {
            float4 a = *reinterpret_cast<const float4*>(&sA[kk][mg << 2]);
            float w = sW[kk][nn];
            acc.x = fmaf(a.x, w, acc.x);
            acc.y = fmaf(a.y, w, acc.y);
            acc.z = fmaf(a.z, w, acc.z);
            acc.w = fmaf(a.w, w, acc.w);
        }
        __syncthreads();
    }

    const int gn = n0 + nn;
    const float bv = bias[gn];
    float out[4] = {acc.x + bv, acc.y + bv, acc.z + bv, acc.w + bv};
    if (act) {
        #pragma unroll
        for (int j = 0; j < 4; ++j) out[j] = tanhf(out[j]);
    }

    float* C;
    int ldc;
    if (outSel == 0)      { C = g_feed; ldc = HH; }
    else if (outSel == 1) { C = g_gx;   ldc = 3 * HH; }
    else if (outSel == 2) { C = g_gh;   ldc = 3 * HH; }
    else                  { C = Cext;   ldc = TD * HH; }

    const int m0 = mg << 2;
    #pragma unroll
    for (int j = 0; j < 4; ++j) {
        C[(m0 + j) * ldc + gn] = out[j];
        if (outSel == 3) g_ifeed[(m0 + j) * HH + gn] = out[j];
    }
}

// ---------------- fused GRU-gate + attention kernel (one block per batch row) -------
// Reads g_gx, g_gh, g_h; writes g_h (= h_new) and g_value.
__global__ __launch_bounds__(256)
void attn64(const float* __restrict__ o_enc)
{
    __shared__ __align__(16) float sh[HH];   // h_new
    __shared__ float sp[TE];                 // scores -> probs
    __shared__ float red[40];

    const int b = blockIdx.x;
    const int tid = threadIdx.x;
    const int w = tid >> 5;
    const int l = tid & 31;

    // --- phase 1: GRU elementwise (reset_after=True) -> h_new
    #pragma unroll
    for (int r = 0; r < 4; ++r) {
        int i = (r << 8) + tid;
        float xz = g_gx[b * 3 * HH + i];
        float xr = g_gx[b * 3 * HH + HH + i];
        float xh = g_gx[b * 3 * HH + 2 * HH + i];
        float hz = g_gh[b * 3 * HH + i];
        float hr = g_gh[b * 3 * HH + HH + i];
        float hh2 = g_gh[b * 3 * HH + 2 * HH + i];
        float hp = g_h[b * HH + i];
        float z  = 1.0f / (1.0f + expf(-(xz + hz)));
        float rr = 1.0f / (1.0f + expf(-(xr + hr)));
        float hc = tanhf(xh + rr * hh2);
        float hn = z * hp + (1.0f - z) * hc;
        sh[i] = hn;
        g_h[b * HH + i] = hn;
    }
    __syncthreads();

    // --- phase 2: scores[t] = h_new . o_enc[b,t,:]  (warp per row, 32 rows/warp)
    const float* ob = o_enc + (size_t)b * TE * HH;
    for (int tt = 0; tt < 32; ++tt) {
        int t = (w << 5) + tt;
        const float* orow = ob + t * HH;
        float s = 0.0f;
        #pragma unroll
        for (int jj = 0; jj < 8; ++jj) {
            int i = (jj << 7) + (l << 2);
            float4 o4 = *reinterpret_cast<const float4*>(orow + i);
            float4 h4 = *reinterpret_cast<const float4*>(sh + i);
            s += o4.x * h4.x + o4.y * h4.y + o4.z * h4.z + o4.w * h4.w;
        }
        #pragma unroll
        for (int off = 16; off > 0; off >>= 1)
            s += __shfl_xor_sync(0xffffffffu, s, off);
        if (l == 0) sp[t] = s;
    }
    __syncthreads();

    // --- phase 3: softmax over 256 (one thread per t)
    float v = sp[tid];
    float m = v;
    #pragma unroll
    for (int off = 16; off > 0; off >>= 1)
        m = fmaxf(m, __shfl_xor_sync(0xffffffffu, m, off));
    if (l == 0) red[w] = m;
    __syncthreads();
    if (tid < 32) {
        float mm = (tid < 8) ? red[tid] : -1e30f;
        #pragma unroll
        for (int off = 4; off > 0; off >>= 1)
            mm = fmaxf(mm, __shfl_xor_sync(0xffffffffu, mm, off));
        if (tid == 0) red[32] = mm;
    }
    __syncthreads();
    float gmax = red[32];
    float e = expf(v - gmax);
    float ssum = e;
    #pragma unroll
    for (int off = 16; off > 0; off >>= 1)
        ssum += __shfl_xor_sync(0xffffffffu, ssum, off);
    if (l == 0) red[8 + w] = ssum;
    __syncthreads();
    if (tid < 32) {
        float s2 = (tid < 8) ? red[8 + tid] : 0.0f;
        #pragma unroll
        for (int off = 4; off > 0; off >>= 1)
            s2 += __shfl_xor_sync(0xffffffffu, s2, off);
        if (tid == 0) red[33] = 1.0f / s2;
    }
    __syncthreads();
    sp[tid] = e * red[33];
    __syncthreads();

    // --- phase 4: value = sum_t p[t] * o_enc[b,t,:]  (thread per 4 strided cols)
    float a0 = 0.f, a1 = 0.f, a2 = 0.f, a3 = 0.f;
    for (int t = 0; t < TE; ++t) {
        float p = sp[t];
        const float* orow = ob + t * HH;
        a0 = fmaf(p, orow[tid], a0);
        a1 = fmaf(p, orow[256 + tid], a1);
        a2 = fmaf(p, orow[512 + tid], a2);
        a3 = fmaf(p, orow[768 + tid], a3);
    }
    g_value[b * HH + tid]       = a0;
    g_value[b * HH + 256 + tid] = a1;
    g_value[b * HH + 512 + tid] = a2;
    g_value[b * HH + 768 + tid] = a3;
}

// ---------------- launcher ----------------------------------------------------------
extern "C" void kernel_launch(void* const* d_in, const int* in_sizes, int n_in,
                              void* d_out, int out_size)
{
    const float* x      = (const float*)d_in[0];   // [B, TD, DX]
    const float* o_enc  = (const float*)d_in[1];   // [B, TE, H]
    const float* h_enc  = (const float*)d_in[2];   // [B, H]
    const float* Wfeed  = (const float*)d_in[3];   // [H, H]
    const float* bfeed  = (const float*)d_in[4];   // [H]
    const float* Wx     = (const float*)d_in[5];   // [2H, 3H]
    const float* Wh     = (const float*)d_in[6];   // [H, 3H]
    const float* bxi    = (const float*)d_in[7];   // [3H]
    const float* bhr    = (const float*)d_in[8];   // [3H]
    const float* Watt   = (const float*)d_in[9];   // [2H, H]
    const float* batt   = (const float*)d_in[10];  // [H]
    float* out = (float*)d_out;                    // [B, TD, H]

    init64<<<64, 1024>>>(h_enc);

    for (int t = 0; t < TD; ++t) {
        // feed = tanh(ifeed @ Wfeed + bfeed)
        gemm64<<<HH / 8, 128>>>(nullptr, Wfeed, bfeed, nullptr,
                                HH, HH, 0, /*aSel=*/0, /*outSel=*/0, /*act=*/1);
        // gx = [feed | x_t] @ Wx + bxi
        gemm64<<<(3 * HH) / 8, 128>>>(x + (size_t)t * DX, Wx, bxi, nullptr,
                                      2 * HH, 3 * HH, TD * DX, /*aSel=*/1, /*outSel=*/1, 0);
        // gh = h @ Wh + bhr
        gemm64<<<(3 * HH) / 8, 128>>>(nullptr, Wh, bhr, nullptr,
                                      HH, 3 * HH, 0, /*aSel=*/2, /*outSel=*/2, 0);
        // GRU gates -> h_new; attention -> value   (updates g_h, g_value)
        attn64<<<BB, 256>>>(o_enc);
        // h_att = tanh([value | h_new] @ Watt + batt) -> out[:,t,:] and g_ifeed
        gemm64<<<HH / 8, 128>>>(nullptr, Watt, batt, out + (size_t)t * HH,
                                2 * HH, HH, HH, /*aSel=*/3, /*outSel=*/3, /*act=*/1);
    }
}

// round 5
// speedup vs baseline: 1.7384x; 1.7384x over previous
#include <cuda_runtime.h>
#include <math.h>
#include <stdint.h>

#define BB 64
#define TD 128
#define TE 256
#define DX 1024
#define HH 1024
#define N3 3072

// ---------------- persistent state (static device globals; no allocations) ---------
__device__ float g_h[BB * HH];
__device__ float g_ifeed[BB * HH];
__device__ float g_feed[BB * HH];
__device__ float g_gx[BB * N3];
__device__ float g_gh[BB * N3];
__device__ float g_value[BB * HH];
__device__ float g_gxx[(size_t)TD * BB * N3];   // 96 MB: x_t @ Wx[1024:] + bxi, all t

// ---------------- init --------------------------------------------------------------
__global__ void init64(const float* __restrict__ h_enc) {
    int idx = blockIdx.x * blockDim.x + threadIdx.x;
    if (idx < BB * HH) {
        g_h[idx] = h_enc[idx];
        g_ifeed[idx] = 0.0f;
    }
}

// ---------------- FFMA2 skinny GEMM -------------------------------------------------
// Block: 256 threads, computes C[64, 16] tile. Thread: 4 m-rows (2 f32x2 accs) x 1 col.
// smem: A transposed [k][m] stride 68 floats (16B-aligned rows, low-conflict),
//       W duplicated [k][2n] so one ld.shared.b64 yields (w,w) — no pack movs.
// Inner loop per k: 1 LDS.128 + 1 LDS.64 + 2 FFMA2 = 4 issues vs 4-cyc pipe budget.
#define M_PRE  0   // g_gxx[t] = x_t @ Wx[1024:] + bxi     (grid: 192 x 128)
#define M_FEED 1   // g_feed = tanh(g_ifeed @ Wfeed + bfeed)  (grid: 64)
#define M_GXGH 2   // y=0: g_gx = g_feed @ Wx[:1024] + gxx[t]; y=1: g_gh = g_h @ Wh + bhr (grid: 192 x 2)
#define M_HATT 3   // h_att = tanh([value|h] @ Watt + batt) -> out[:,t,:], g_ifeed (grid: 64)

template <int MODE>
__global__ __launch_bounds__(256, 2)
void gstep(const float* __restrict__ Xa,
           const float* __restrict__ Wa, const float* __restrict__ Ba,
           const float* __restrict__ Wb, const float* __restrict__ Bb,
           float* __restrict__ outp, int t)
{
    constexpr int KDIM = (MODE == M_HATT) ? 2 * HH : HH;
    constexpr int NDIM = (MODE == M_PRE || MODE == M_GXGH) ? N3 : HH;

    __shared__ __align__(16) float sA[32 * 68];
    __shared__ __align__(8)  float sW[32 * 32];

    const int tid = threadIdx.x;
    const int mg  = tid & 15;      // 4 m-rows: mg*4 .. mg*4+3
    const int ng  = tid >> 4;      // 0..15
    const int n0  = blockIdx.x * 16;
    const int n   = n0 + ng;

    const float* Aptr = nullptr; int lda = HH;
    const float* Wptr; const float* bptr;
    const float* addptr = nullptr;
    float* Cptr; int ldc;

    if (MODE == M_PRE) {
        Aptr = Xa + (size_t)blockIdx.y * DX; lda = TD * DX;
        Wptr = Wa; bptr = Ba;
        Cptr = g_gxx + (size_t)blockIdx.y * BB * N3; ldc = N3;
    } else if (MODE == M_FEED) {
        Aptr = g_ifeed; Wptr = Wa; bptr = Ba;
        Cptr = g_feed; ldc = HH;
    } else if (MODE == M_GXGH) {
        if (blockIdx.y == 0) {
            Aptr = g_feed; Wptr = Wa; bptr = nullptr;
            addptr = g_gxx + (size_t)t * BB * N3;
            Cptr = g_gx;
        } else {
            Aptr = g_h; Wptr = Wb; bptr = Bb;
            Cptr = g_gh;
        }
        ldc = N3;
    } else { // M_HATT
        Wptr = Wa; bptr = Ba;
        Cptr = outp + (size_t)t * HH; ldc = TD * HH;
    }

    uint32_t sAb = (uint32_t)__cvta_generic_to_shared(sA);
    uint32_t sWb = (uint32_t)__cvta_generic_to_shared(sW);
    const uint32_t ra = sAb + mg * 16;   // sA[k][mg*4], k-stride 272B
    const uint32_t rw = sWb + ng * 8;    // sW[k][2*ng], k-stride 128B

    uint64_t acc0 = 0ull, acc1 = 0ull;   // packed (f32, f32) pairs, zero == (0.f, 0.f)

    for (int k0 = 0; k0 < KDIM; k0 += 32) {
        const float* At; int kloc;
        if (MODE == M_HATT) {
            At = (k0 < HH) ? g_value : g_h;
            kloc = k0 & (HH - 1);
        } else {
            At = Aptr; kloc = k0;
        }

        // A tile 64x32 -> transposed smem [k][m], stride 68
        #pragma unroll
        for (int it = 0; it < 2; ++it) {
            int idx = it * 256 + tid;
            int m = idx >> 3;
            int c = idx & 7;
            float4 v = *reinterpret_cast<const float4*>(At + (size_t)m * lda + kloc + c * 4);
            sA[(c * 4 + 0) * 68 + m] = v.x;
            sA[(c * 4 + 1) * 68 + m] = v.y;
            sA[(c * 4 + 2) * 68 + m] = v.z;
            sA[(c * 4 + 3) * 68 + m] = v.w;
        }
        // W tile 32x16, duplicated -> smem [k][2n]
        #pragma unroll
        for (int it = 0; it < 2; ++it) {
            int idx = it * 256 + tid;
            int kk = idx >> 4;
            int nn = idx & 15;
            float w = Wptr[(size_t)(k0 + kk) * NDIM + n0 + nn];
            *reinterpret_cast<float2*>(&sW[kk * 32 + nn * 2]) = make_float2(w, w);
        }
        __syncthreads();

        uint32_t pa = ra, pw = rw;
        #pragma unroll
        for (int kk = 0; kk < 32; ++kk) {
            uint64_t a01, a23, w2;
            asm volatile("ld.shared.v2.b64 {%0,%1},[%2];" : "=l"(a01), "=l"(a23) : "r"(pa));
            asm volatile("ld.shared.b64 %0,[%1];" : "=l"(w2) : "r"(pw));
            asm("fma.rn.f32x2 %0, %1, %2, %0;" : "+l"(acc0) : "l"(a01), "l"(w2));
            asm("fma.rn.f32x2 %0, %1, %2, %0;" : "+l"(acc1) : "l"(a23), "l"(w2));
            pa += 272; pw += 128;
        }
        __syncthreads();
    }

    // epilogue
    float2 f0 = *reinterpret_cast<float2*>(&acc0);
    float2 f1 = *reinterpret_cast<float2*>(&acc1);
    float o[4] = {f0.x, f0.y, f1.x, f1.y};
    const float bv = bptr ? bptr[n] : 0.0f;
    #pragma unroll
    for (int j = 0; j < 4; ++j) {
        int m = mg * 4 + j;
        float v = o[j] + bv;
        if (MODE == M_GXGH) { if (addptr) v += addptr[(size_t)m * N3 + n]; }
        if (MODE == M_FEED || MODE == M_HATT) v = tanhf(v);
        Cptr[(size_t)m * ldc + n] = v;
        if (MODE == M_HATT) g_ifeed[m * HH + n] = v;
    }
}

// ---------------- fused GRU-gate + attention (one block per batch row) --------------
__global__ __launch_bounds__(256)
void attn64(const float* __restrict__ o_enc)
{
    __shared__ __align__(16) float sh[HH];   // h_new
    __shared__ float sp[TE];                 // scores -> probs
    __shared__ float red[40];

    const int b = blockIdx.x;
    const int tid = threadIdx.x;
    const int w = tid >> 5;
    const int l = tid & 31;

    // phase 1: GRU elementwise (reset_after=True)
    #pragma unroll
    for (int r = 0; r < 4; ++r) {
        int i = (r << 8) + tid;
        float xz  = g_gx[b * N3 + i];
        float xr  = g_gx[b * N3 + HH + i];
        float xh  = g_gx[b * N3 + 2 * HH + i];
        float hz  = g_gh[b * N3 + i];
        float hr  = g_gh[b * N3 + HH + i];
        float hh2 = g_gh[b * N3 + 2 * HH + i];
        float hp  = g_h[b * HH + i];
        float z  = 1.0f / (1.0f + expf(-(xz + hz)));
        float rr = 1.0f / (1.0f + expf(-(xr + hr)));
        float hc = tanhf(xh + rr * hh2);
        float hn = z * hp + (1.0f - z) * hc;
        sh[i] = hn;
        g_h[b * HH + i] = hn;
    }
    __syncthreads();

    // phase 2: scores[t] = h_new . o_enc[b,t,:]
    const float* ob = o_enc + (size_t)b * TE * HH;
    for (int tt = 0; tt < 32; ++tt) {
        int t = (w << 5) + tt;
        const float* orow = ob + t * HH;
        float s = 0.0f;
        #pragma unroll
        for (int jj = 0; jj < 8; ++jj) {
            int i = (jj << 7) + (l << 2);
            float4 o4 = *reinterpret_cast<const float4*>(orow + i);
            float4 h4 = *reinterpret_cast<const float4*>(sh + i);
            s += o4.x * h4.x + o4.y * h4.y + o4.z * h4.z + o4.w * h4.w;
        }
        #pragma unroll
        for (int off = 16; off > 0; off >>= 1)
            s += __shfl_xor_sync(0xffffffffu, s, off);
        if (l == 0) sp[t] = s;
    }
    __syncthreads();

    // phase 3: softmax over 256
    float v = sp[tid];
    float m = v;
    #pragma unroll
    for (int off = 16; off > 0; off >>= 1)
        m = fmaxf(m, __shfl_xor_sync(0xffffffffu, m, off));
    if (l == 0) red[w] = m;
    __syncthreads();
    if (tid < 32) {
        float mm = (tid < 8) ? red[tid] : -1e30f;
        #pragma unroll
        for (int off = 4; off > 0; off >>= 1)
            mm = fmaxf(mm, __shfl_xor_sync(0xffffffffu, mm, off));
        if (tid == 0) red[32] = mm;
    }
    __syncthreads();
    float gmax = red[32];
    float e = expf(v - gmax);
    float ssum = e;
    #pragma unroll
    for (int off = 16; off > 0; off >>= 1)
        ssum += __shfl_xor_sync(0xffffffffu, ssum, off);
    if (l == 0) red[8 + w] = ssum;
    __syncthreads();
    if (tid < 32) {
        float s2 = (tid < 8) ? red[8 + tid] : 0.0f;
        #pragma unroll
        for (int off = 4; off > 0; off >>= 1)
            s2 += __shfl_xor_sync(0xffffffffu, s2, off);
        if (tid == 0) red[33] = 1.0f / s2;
    }
    __syncthreads();
    sp[tid] = e * red[33];
    __syncthreads();

    // phase 4: value = sum_t p[t] * o_enc[b,t,:]  — float4 coalesced, cols 4*tid..+3
    float4 a = make_float4(0.f, 0.f, 0.f, 0.f);
    const int col = tid << 2;
    for (int t = 0; t < TE; ++t) {
        float p = sp[t];
        float4 o4 = *reinterpret_cast<const float4*>(ob + t * HH + col);
        a.x = fmaf(p, o4.x, a.x);
        a.y = fmaf(p, o4.y, a.y);
        a.z = fmaf(p, o4.z, a.z);
        a.w = fmaf(p, o4.w, a.w);
    }
    *reinterpret_cast<float4*>(&g_value[b * HH + col]) = a;
}

// ---------------- launcher ----------------------------------------------------------
extern "C" void kernel_launch(void* const* d_in, const int* in_sizes, int n_in,
                              void* d_out, int out_size)
{
    const float* x      = (const float*)d_in[0];   // [B, TD, DX]
    const float* o_enc  = (const float*)d_in[1];   // [B, TE, H]
    const float* h_enc  = (const float*)d_in[2];   // [B, H]
    const float* Wfeed  = (const float*)d_in[3];   // [H, H]
    const float* bfeed  = (const float*)d_in[4];   // [H]
    const float* Wx     = (const float*)d_in[5];   // [2H, 3H]  rows 0..1023: feed, 1024..2047: x
    const float* Wh     = (const float*)d_in[6];   // [H, 3H]
    const float* bxi    = (const float*)d_in[7];   // [3H]
    const float* bhr    = (const float*)d_in[8];   // [3H]
    const float* Watt   = (const float*)d_in[9];   // [2H, H]
    const float* batt   = (const float*)d_in[10];  // [H]
    float* out = (float*)d_out;                    // [B, TD, H]

    init64<<<64, 1024>>>(h_enc);

    // precompute g_gxx[t] = x_t @ Wx[1024:] + bxi, for all t (recurrence-independent)
    gstep<M_PRE><<<dim3(N3 / 16, TD), 256>>>(x, Wx + (size_t)HH * N3, bxi,
                                             nullptr, nullptr, nullptr, 0);

    for (int t = 0; t < TD; ++t) {
        gstep<M_FEED><<<HH / 16, 256>>>(nullptr, Wfeed, bfeed,
                                        nullptr, nullptr, nullptr, t);
        gstep<M_GXGH><<<dim3(N3 / 16, 2), 256>>>(nullptr, Wx, nullptr,
                                                 Wh, bhr, nullptr, t);
        attn64<<<BB, 256>>>(o_enc);
        gstep<M_HATT><<<HH / 16, 256>>>(nullptr, Watt, batt,
                                        nullptr, nullptr, out, t);
    }
}

// round 6
// speedup vs baseline: 2.6311x; 1.5136x over previous
#include <cuda_runtime.h>
#include <math.h>
#include <stdint.h>

#define BB 64
#define TD 128
#define TE 256
#define DX 1024
#define HH 1024
#define N3 3072

// ---------------- persistent state (static device globals; no allocations) ---------
__device__ float g_h[BB * HH];
__device__ float g_ifeed[BB * HH];
__device__ float g_feed[BB * HH];
__device__ float g_gx[BB * N3];
__device__ float g_gh[BB * N3];
__device__ float g_value[BB * HH];
__device__ float g_gxx[(size_t)TD * BB * N3];   // 96 MB: x_t @ Wx[1024:] + bxi, all t

// ---------------- init --------------------------------------------------------------
__global__ void init64(const float* __restrict__ h_enc) {
    int idx = blockIdx.x * blockDim.x + threadIdx.x;
    if (idx < BB * HH) {
        g_h[idx] = h_enc[idx];
        g_ifeed[idx] = 0.0f;
    }
}

__device__ __forceinline__ void ffma2(unsigned long long& acc,
                                      unsigned long long a, unsigned long long b) {
    asm("fma.rn.f32x2 %0, %1, %2, %0;" : "+l"(acc) : "l"(a), "l"(b));
}
__device__ __forceinline__ float2 upk(unsigned long long v) {
    float2 f; f.x = __uint_as_float((unsigned)(v & 0xffffffffull));
    f.y = __uint_as_float((unsigned)(v >> 32)); return f;
}

// ---------------- FFMA2 skinny GEMM, 2-way in-block K-split -------------------------
// Block = 256 threads = two 4-warp halves (kh), each half computes the full 64x16
// C tile over its half of K; halves combined through smem at the end.
// Within a half: warp w covers m-patch [16w,16w+16), lane = (mgl 0..3) x (ngl 0..7),
// thread tile 4m x 2n. Per k: LDS.128(A: 4 consecutive m as 2 f32x2) +
// LDS.128(W-dup: w_n0,w_n0,w_n1,w_n1) + 4 FFMA2.
#define M_PRE  0   // g_gxx[t] = x_t @ Wx[1024:] + bxi                  grid (192, 128)
#define M_FEED 1   // g_feed = tanh(g_ifeed @ Wfeed + bfeed)            grid 64
#define M_GXGH 2   // y0: g_gx = g_feed @ Wx[:1024] + gxx[t]; y1: g_gh  grid (192, 2)
#define M_HATT 3   // tanh([value|h] @ Watt + batt) -> out[:,t,:], g_ifeed   grid 64

template <int MODE>
__global__ __launch_bounds__(256, 3)
void gstep(const float* __restrict__ Xa,
           const float* __restrict__ Wa, const float* __restrict__ Ba,
           const float* __restrict__ Wb, const float* __restrict__ Bb,
           float* __restrict__ outp, int t)
{
    constexpr int KDIM  = (MODE == M_HATT) ? 2 * HH : HH;
    constexpr int KHALF = KDIM / 2;
    constexpr int KT    = KHALF / 32;
    constexpr int NDIM  = (MODE == M_PRE || MODE == M_GXGH) ? N3 : HH;

    __shared__ __align__(16) float sA[2][32][68];   // [kh][k][m], padded
    __shared__ __align__(16) float sW[2][32][32];   // [kh][k][2n] duplicated

    const int tid  = threadIdx.x;
    const int kh   = tid >> 7;        // k-split half
    const int lt   = tid & 127;
    const int lane = lt & 31;
    const int w    = lt >> 5;         // warp within half (0..3) == real warp % 4
    const int mgl  = lane & 3;
    const int ngl  = lane >> 2;
    const int m0   = w * 16 + mgl * 4;
    const int n0   = blockIdx.x * 16;
    const int kbase = kh * KHALF;

    const float* Aptr = nullptr; int lda = HH; int aoff = kbase;
    const float* Wptr; const float* bptr = nullptr; const float* addptr = nullptr;
    float* Cptr; int ldc;

    if (MODE == M_PRE) {
        Aptr = Xa + (size_t)blockIdx.y * DX; lda = TD * DX;
        Wptr = Wa; bptr = Ba;
        Cptr = g_gxx + (size_t)blockIdx.y * BB * N3; ldc = N3;
    } else if (MODE == M_FEED) {
        Aptr = g_ifeed; Wptr = Wa; bptr = Ba;
        Cptr = g_feed; ldc = HH;
    } else if (MODE == M_GXGH) {
        if (blockIdx.y == 0) {
            Aptr = g_feed; Wptr = Wa;
            addptr = g_gxx + (size_t)t * BB * N3;
            Cptr = g_gx;
        } else {
            Aptr = g_h; Wptr = Wb; bptr = Bb;
            Cptr = g_gh;
        }
        ldc = N3;
    } else { // M_HATT: half 0 reads g_value (k 0..1023), half 1 reads g_h
        Aptr = kh ? g_h : g_value; lda = HH; aoff = 0;
        Wptr = Wa; bptr = Ba;
        Cptr = outp + (size_t)t * HH; ldc = TD * HH;
    }

    float4 rA[4];
    float  rW[4];

    auto loadT = [&](int kt) {
        #pragma unroll
        for (int it = 0; it < 4; ++it) {
            int idx = it * 128 + lt;
            int m = idx >> 3;
            int c = idx & 7;
            rA[it] = *reinterpret_cast<const float4*>(
                Aptr + (size_t)m * lda + aoff + kt * 32 + c * 4);
        }
        #pragma unroll
        for (int it = 0; it < 4; ++it) {
            int idx = it * 128 + lt;
            int kk = idx >> 4;
            int nn = idx & 15;
            rW[it] = Wptr[(size_t)(kbase + kt * 32 + kk) * NDIM + n0 + nn];
        }
    };
    auto storeT = [&]() {
        #pragma unroll
        for (int it = 0; it < 4; ++it) {
            int idx = it * 128 + lt;
            int m = idx >> 3;
            int c = idx & 7;
            sA[kh][c * 4 + 0][m] = rA[it].x;
            sA[kh][c * 4 + 1][m] = rA[it].y;
            sA[kh][c * 4 + 2][m] = rA[it].z;
            sA[kh][c * 4 + 3][m] = rA[it].w;
        }
        #pragma unroll
        for (int it = 0; it < 4; ++it) {
            int idx = it * 128 + lt;
            int kk = idx >> 4;
            int nn = idx & 15;
            *reinterpret_cast<float2*>(&sW[kh][kk][nn * 2]) = make_float2(rW[it], rW[it]);
        }
    };

    unsigned long long acc00 = 0, acc10 = 0, acc01 = 0, acc11 = 0;

    loadT(0);
    storeT();
    __syncthreads();

    #pragma unroll 1
    for (int kt = 0; kt < KT; ++kt) {
        if (kt + 1 < KT) loadT(kt + 1);     // global prefetch, hidden under compute
        #pragma unroll
        for (int kk = 0; kk < 32; ++kk) {
            ulonglong2 av = *reinterpret_cast<const ulonglong2*>(&sA[kh][kk][m0]);
            ulonglong2 wv = *reinterpret_cast<const ulonglong2*>(&sW[kh][kk][ngl * 4]);
            ffma2(acc00, av.x, wv.x);
            ffma2(acc10, av.y, wv.x);
            ffma2(acc01, av.x, wv.y);
            ffma2(acc11, av.y, wv.y);
        }
        __syncthreads();                    // done reading this tile
        if (kt + 1 < KT) storeT();
        __syncthreads();                    // tile ready
    }

    // ---- combine the two K-halves through smem (overlay on sW[0], 4KB) ----
    unsigned long long* sred = reinterpret_cast<unsigned long long*>(&sW[0][0][0]);
    if (kh == 1) {
        unsigned long long* d = sred + lt * 4;
        d[0] = acc00; d[1] = acc10; d[2] = acc01; d[3] = acc11;
    }
    __syncthreads();
    if (kh == 0) {
        const unsigned long long* s = sred + lt * 4;
        float2 o00 = upk(acc00), o10 = upk(acc10), o01 = upk(acc01), o11 = upk(acc11);
        float2 p00 = upk(s[0]),  p10 = upk(s[1]),  p01 = upk(s[2]),  p11 = upk(s[3]);
        float vals[2][4] = {
            { o00.x + p00.x, o00.y + p00.y, o10.x + p10.x, o10.y + p10.y },
            { o01.x + p01.x, o01.y + p01.y, o11.x + p11.x, o11.y + p11.y }
        };
        #pragma unroll
        for (int jj = 0; jj < 2; ++jj) {
            const int n = n0 + ngl * 2 + jj;
            const float bv = bptr ? bptr[n] : 0.0f;
            #pragma unroll
            for (int j = 0; j < 4; ++j) {
                const int m = m0 + j;
                float v = vals[jj][j] + bv;
                if (MODE == M_GXGH) { if (addptr) v += addptr[(size_t)m * N3 + n]; }
                if (MODE == M_FEED || MODE == M_HATT) v = tanhf(v);
                Cptr[(size_t)m * ldc + n] = v;
                if (MODE == M_HATT) g_ifeed[m * HH + n] = v;
            }
        }
    }
}

// ---------------- fused GRU-gate + attention (one block per batch row) --------------
__global__ __launch_bounds__(256)
void attn64(const float* __restrict__ o_enc)
{
    __shared__ __align__(16) float sh[HH];
    __shared__ float sp[TE];
    __shared__ float red[40];

    const int b = blockIdx.x;
    const int tid = threadIdx.x;
    const int w = tid >> 5;
    const int l = tid & 31;

    // phase 1: GRU elementwise (reset_after=True)
    #pragma unroll
    for (int r = 0; r < 4; ++r) {
        int i = (r << 8) + tid;
        float xz  = g_gx[b * N3 + i];
        float xr  = g_gx[b * N3 + HH + i];
        float xh  = g_gx[b * N3 + 2 * HH + i];
        float hz  = g_gh[b * N3 + i];
        float hr  = g_gh[b * N3 + HH + i];
        float hh2 = g_gh[b * N3 + 2 * HH + i];
        float hp  = g_h[b * HH + i];
        float z  = 1.0f / (1.0f + expf(-(xz + hz)));
        float rr = 1.0f / (1.0f + expf(-(xr + hr)));
        float hc = tanhf(xh + rr * hh2);
        float hn = z * hp + (1.0f - z) * hc;
        sh[i] = hn;
        g_h[b * HH + i] = hn;
    }
    __syncthreads();

    // phase 2: scores
    const float* ob = o_enc + (size_t)b * TE * HH;
    for (int tt = 0; tt < 32; ++tt) {
        int t = (w << 5) + tt;
        const float* orow = ob + t * HH;
        float s = 0.0f;
        #pragma unroll
        for (int jj = 0; jj < 8; ++jj) {
            int i = (jj << 7) + (l << 2);
            float4 o4 = *reinterpret_cast<const float4*>(orow + i);
            float4 h4 = *reinterpret_cast<const float4*>(sh + i);
            s += o4.x * h4.x + o4.y * h4.y + o4.z * h4.z + o4.w * h4.w;
        }
        #pragma unroll
        for (int off = 16; off > 0; off >>= 1)
            s += __shfl_xor_sync(0xffffffffu, s, off);
        if (l == 0) sp[t] = s;
    }
    __syncthreads();

    // phase 3: softmax over 256
    float v = sp[tid];
    float m = v;
    #pragma unroll
    for (int off = 16; off > 0; off >>= 1)
        m = fmaxf(m, __shfl_xor_sync(0xffffffffu, m, off));
    if (l == 0) red[w] = m;
    __syncthreads();
    if (tid < 32) {
        float mm = (tid < 8) ? red[tid] : -1e30f;
        #pragma unroll
        for (int off = 4; off > 0; off >>= 1)
            mm = fmaxf(mm, __shfl_xor_sync(0xffffffffu, mm, off));
        if (tid == 0) red[32] = mm;
    }
    __syncthreads();
    float gmax = red[32];
    float e = expf(v - gmax);
    float ssum = e;
    #pragma unroll
    for (int off = 16; off > 0; off >>= 1)
        ssum += __shfl_xor_sync(0xffffffffu, ssum, off);
    if (l == 0) red[8 + w] = ssum;
    __syncthreads();
    if (tid < 32) {
        float s2 = (tid < 8) ? red[8 + tid] : 0.0f;
        #pragma unroll
        for (int off = 4; off > 0; off >>= 1)
            s2 += __shfl_xor_sync(0xffffffffu, s2, off);
        if (tid == 0) red[33] = 1.0f / s2;
    }
    __syncthreads();
    sp[tid] = e * red[33];
    __syncthreads();

    // phase 4: value = sum_t p[t] * o_enc[b,t,:]
    float4 a = make_float4(0.f, 0.f, 0.f, 0.f);
    const int col = tid << 2;
    #pragma unroll 4
    for (int t = 0; t < TE; ++t) {
        float p = sp[t];
        float4 o4 = *reinterpret_cast<const float4*>(ob + t * HH + col);
        a.x = fmaf(p, o4.x, a.x);
        a.y = fmaf(p, o4.y, a.y);
        a.z = fmaf(p, o4.z, a.z);
        a.w = fmaf(p, o4.w, a.w);
    }
    *reinterpret_cast<float4*>(&g_value[b * HH + col]) = a;
}

// ---------------- launcher ----------------------------------------------------------
extern "C" void kernel_launch(void* const* d_in, const int* in_sizes, int n_in,
                              void* d_out, int out_size)
{
    const float* x      = (const float*)d_in[0];
    const float* o_enc  = (const float*)d_in[1];
    const float* h_enc  = (const float*)d_in[2];
    const float* Wfeed  = (const float*)d_in[3];
    const float* bfeed  = (const float*)d_in[4];
    const float* Wx     = (const float*)d_in[5];
    const float* Wh     = (const float*)d_in[6];
    const float* bxi    = (const float*)d_in[7];
    const float* bhr    = (const float*)d_in[8];
    const float* Watt   = (const float*)d_in[9];
    const float* batt   = (const float*)d_in[10];
    float* out = (float*)d_out;

    init64<<<64, 1024>>>(h_enc);

    // precompute g_gxx[t] = x_t @ Wx[1024:] + bxi for all t (recurrence-independent)
    gstep<M_PRE><<<dim3(N3 / 16, TD), 256>>>(x, Wx + (size_t)HH * N3, bxi,
                                             nullptr, nullptr, nullptr, 0);

    for (int t = 0; t < TD; ++t) {
        gstep<M_FEED><<<HH / 16, 256>>>(nullptr, Wfeed, bfeed,
                                        nullptr, nullptr, nullptr, t);
        gstep<M_GXGH><<<dim3(N3 / 16, 2), 256>>>(nullptr, Wx, nullptr,
                                                 Wh, bhr, nullptr, t);
        attn64<<<BB, 256>>>(o_enc);
        gstep<M_HATT><<<HH / 16, 256>>>(nullptr, Watt, batt,
                                        nullptr, nullptr, out, t);
    }
}

// round 7
// speedup vs baseline: 2.6317x; 1.0002x over previous
#include <cuda_runtime.h>
#include <math.h>
#include <stdint.h>

#define BB 64
#define TD 128
#define TE 256
#define DX 1024
#define HH 1024
#define N3 3072

// ---------------- persistent state (static device globals; no allocations) ---------
__device__ float g_h[BB * HH];
__device__ float g_ifeed[BB * HH];
__device__ float g_feed[BB * HH];
__device__ float g_gx[BB * N3];
__device__ float g_gh[BB * N3];
__device__ float g_value[BB * HH];
__device__ float g_gxx[(size_t)TD * BB * N3];   // 96 MB: x_t @ Wx[1024:] + bxi, all t

// ---------------- init --------------------------------------------------------------
__global__ void init64(const float* __restrict__ h_enc) {
    int idx = blockIdx.x * blockDim.x + threadIdx.x;
    if (idx < BB * HH) {
        g_h[idx] = h_enc[idx];
        g_ifeed[idx] = 0.0f;
    }
}

__device__ __forceinline__ void ffma2(unsigned long long& acc,
                                      unsigned long long a, unsigned long long b) {
    asm("fma.rn.f32x2 %0, %1, %2, %0;" : "+l"(acc) : "l"(a), "l"(b));
}
__device__ __forceinline__ float2 upk(unsigned long long v) {
    float2 f; f.x = __uint_as_float((unsigned)(v & 0xffffffffull));
    f.y = __uint_as_float((unsigned)(v >> 32)); return f;
}

// ---------------- FFMA2 skinny GEMM, 2-way in-block K-split -------------------------
// Block = 256 threads = two 4-warp halves (kh), each half computes the full 64x16
// C tile over its half of K; halves combined through smem at the end.
// Within a half: warp w covers m-patch [16w,16w+16), lane = (mgl 0..3) x (ngl 0..7),
// thread tile 4m x 2n. Per k: LDS.128(A: 4 consecutive m as 2 f32x2) +
// LDS.128(W-dup: w_n0,w_n0,w_n1,w_n1) + 4 FFMA2.
#define M_PRE  0   // g_gxx[t] = x_t @ Wx[1024:] + bxi                  grid (192, 128)
#define M_FEED 1   // g_feed = tanh(g_ifeed @ Wfeed + bfeed)            grid 64
#define M_GXGH 2   // y0: g_gx = g_feed @ Wx[:1024] + gxx[t]; y1: g_gh  grid (192, 2)
#define M_HATT 3   // tanh([value|h] @ Watt + batt) -> out[:,t,:], g_ifeed   grid 64

template <int MODE>
__global__ __launch_bounds__(256, 3)
void gstep(const float* __restrict__ Xa,
           const float* __restrict__ Wa, const float* __restrict__ Ba,
           const float* __restrict__ Wb, const float* __restrict__ Bb,
           float* __restrict__ outp, int t)
{
    constexpr int KDIM  = (MODE == M_HATT) ? 2 * HH : HH;
    constexpr int KHALF = KDIM / 2;
    constexpr int KT    = KHALF / 32;
    constexpr int NDIM  = (MODE == M_PRE || MODE == M_GXGH) ? N3 : HH;

    __shared__ __align__(16) float sA[2][32][68];   // [kh][k][m], padded
    __shared__ __align__(16) float sW[2][32][32];   // [kh][k][2n] duplicated

    const int tid  = threadIdx.x;
    const int kh   = tid >> 7;        // k-split half
    const int lt   = tid & 127;
    const int lane = lt & 31;
    const int w    = lt >> 5;         // warp within half (0..3) == real warp % 4
    const int mgl  = lane & 3;
    const int ngl  = lane >> 2;
    const int m0   = w * 16 + mgl * 4;
    const int n0   = blockIdx.x * 16;
    const int kbase = kh * KHALF;

    const float* Aptr = nullptr; int lda = HH; int aoff = kbase;
    const float* Wptr; const float* bptr = nullptr; const float* addptr = nullptr;
    float* Cptr; int ldc;

    if (MODE == M_PRE) {
        Aptr = Xa + (size_t)blockIdx.y * DX; lda = TD * DX;
        Wptr = Wa; bptr = Ba;
        Cptr = g_gxx + (size_t)blockIdx.y * BB * N3; ldc = N3;
    } else if (MODE == M_FEED) {
        Aptr = g_ifeed; Wptr = Wa; bptr = Ba;
        Cptr = g_feed; ldc = HH;
    } else if (MODE == M_GXGH) {
        if (blockIdx.y == 0) {
            Aptr = g_feed; Wptr = Wa;
            addptr = g_gxx + (size_t)t * BB * N3;
            Cptr = g_gx;
        } else {
            Aptr = g_h; Wptr = Wb; bptr = Bb;
            Cptr = g_gh;
        }
        ldc = N3;
    } else { // M_HATT: half 0 reads g_value (k 0..1023), half 1 reads g_h
        Aptr = kh ? g_h : g_value; lda = HH; aoff = 0;
        Wptr = Wa; bptr = Ba;
        Cptr = outp + (size_t)t * HH; ldc = TD * HH;
    }

    float4 rA[4];
    float  rW[4];

    auto loadT = [&](int kt) {
        #pragma unroll
        for (int it = 0; it < 4; ++it) {
            int idx = it * 128 + lt;
            int m = idx >> 3;
            int c = idx & 7;
            rA[it] = *reinterpret_cast<const float4*>(
                Aptr + (size_t)m * lda + aoff + kt * 32 + c * 4);
        }
        #pragma unroll
        for (int it = 0; it < 4; ++it) {
            int idx = it * 128 + lt;
            int kk = idx >> 4;
            int nn = idx & 15;
            rW[it] = Wptr[(size_t)(kbase + kt * 32 + kk) * NDIM + n0 + nn];
        }
    };
    auto storeT = [&]() {
        #pragma unroll
        for (int it = 0; it < 4; ++it) {
            int idx = it * 128 + lt;
            int m = idx >> 3;
            int c = idx & 7;
            sA[kh][c * 4 + 0][m] = rA[it].x;
            sA[kh][c * 4 + 1][m] = rA[it].y;
            sA[kh][c * 4 + 2][m] = rA[it].z;
            sA[kh][c * 4 + 3][m] = rA[it].w;
        }
        #pragma unroll
        for (int it = 0; it < 4; ++it) {
            int idx = it * 128 + lt;
            int kk = idx >> 4;
            int nn = idx & 15;
            *reinterpret_cast<float2*>(&sW[kh][kk][nn * 2]) = make_float2(rW[it], rW[it]);
        }
    };

    unsigned long long acc00 = 0, acc10 = 0, acc01 = 0, acc11 = 0;

    loadT(0);
    storeT();
    __syncthreads();

    #pragma unroll 1
    for (int kt = 0; kt < KT; ++kt) {
        if (kt + 1 < KT) loadT(kt + 1);     // global prefetch, hidden under compute
        #pragma unroll
        for (int kk = 0; kk < 32; ++kk) {
            ulonglong2 av = *reinterpret_cast<const ulonglong2*>(&sA[kh][kk][m0]);
            ulonglong2 wv = *reinterpret_cast<const ulonglong2*>(&sW[kh][kk][ngl * 4]);
            ffma2(acc00, av.x, wv.x);
            ffma2(acc10, av.y, wv.x);
            ffma2(acc01, av.x, wv.y);
            ffma2(acc11, av.y, wv.y);
        }
        __syncthreads();                    // done reading this tile
        if (kt + 1 < KT) storeT();
        __syncthreads();                    // tile ready
    }

    // ---- combine the two K-halves through smem (overlay on sW[0], 4KB) ----
    unsigned long long* sred = reinterpret_cast<unsigned long long*>(&sW[0][0][0]);
    if (kh == 1) {
        unsigned long long* d = sred + lt * 4;
        d[0] = acc00; d[1] = acc10; d[2] = acc01; d[3] = acc11;
    }
    __syncthreads();
    if (kh == 0) {
        const unsigned long long* s = sred + lt * 4;
        float2 o00 = upk(acc00), o10 = upk(acc10), o01 = upk(acc01), o11 = upk(acc11);
        float2 p00 = upk(s[0]),  p10 = upk(s[1]),  p01 = upk(s[2]),  p11 = upk(s[3]);
        float vals[2][4] = {
            { o00.x + p00.x, o00.y + p00.y, o10.x + p10.x, o10.y + p10.y },
            { o01.x + p01.x, o01.y + p01.y, o11.x + p11.x, o11.y + p11.y }
        };
        #pragma unroll
        for (int jj = 0; jj < 2; ++jj) {
            const int n = n0 + ngl * 2 + jj;
            const float bv = bptr ? bptr[n] : 0.0f;
            #pragma unroll
            for (int j = 0; j < 4; ++j) {
                const int m = m0 + j;
                float v = vals[jj][j] + bv;
                if (MODE == M_GXGH) { if (addptr) v += addptr[(size_t)m * N3 + n]; }
                if (MODE == M_FEED || MODE == M_HATT) v = tanhf(v);
                Cptr[(size_t)m * ldc + n] = v;
                if (MODE == M_HATT) g_ifeed[m * HH + n] = v;
            }
        }
    }
}

// ---------------- fused GRU-gate + attention (one block per batch row) --------------
__global__ __launch_bounds__(256)
void attn64(const float* __restrict__ o_enc)
{
    __shared__ __align__(16) float sh[HH];
    __shared__ float sp[TE];
    __shared__ float red[40];

    const int b = blockIdx.x;
    const int tid = threadIdx.x;
    const int w = tid >> 5;
    const int l = tid & 31;

    // phase 1: GRU elementwise (reset_after=True)
    #pragma unroll
    for (int r = 0; r < 4; ++r) {
        int i = (r << 8) + tid;
        float xz  = g_gx[b * N3 + i];
        float xr  = g_gx[b * N3 + HH + i];
        float xh  = g_gx[b * N3 + 2 * HH + i];
        float hz  = g_gh[b * N3 + i];
        float hr  = g_gh[b * N3 + HH + i];
        float hh2 = g_gh[b * N3 + 2 * HH + i];
        float hp  = g_h[b * HH + i];
        float z  = 1.0f / (1.0f + expf(-(xz + hz)));
        float rr = 1.0f / (1.0f + expf(-(xr + hr)));
        float hc = tanhf(xh + rr * hh2);
        float hn = z * hp + (1.0f - z) * hc;
        sh[i] = hn;
        g_h[b * HH + i] = hn;
    }
    __syncthreads();

    // phase 2: scores
    const float* ob = o_enc + (size_t)b * TE * HH;
    for (int tt = 0; tt < 32; ++tt) {
        int t = (w << 5) + tt;
        const float* orow = ob + t * HH;
        float s = 0.0f;
        #pragma unroll
        for (int jj = 0; jj < 8; ++jj) {
            int i = (jj << 7) + (l << 2);
            float4 o4 = *reinterpret_cast<const float4*>(orow + i);
            float4 h4 = *reinterpret_cast<const float4*>(sh + i);
            s += o4.x * h4.x + o4.y * h4.y + o4.z * h4.z + o4.w * h4.w;
        }
        #pragma unroll
        for (int off = 16; off > 0; off >>= 1)
            s += __shfl_xor_sync(0xffffffffu, s, off);
        if (l == 0) sp[t] = s;
    }
    __syncthreads();

    // phase 3: softmax over 256
    float v = sp[tid];
    float m = v;
    #pragma unroll
    for (int off = 16; off > 0; off >>= 1)
        m = fmaxf(m, __shfl_xor_sync(0xffffffffu, m, off));
    if (l == 0) red[w] = m;
    __syncthreads();
    if (tid < 32) {
        float mm = (tid < 8) ? red[tid] : -1e30f;
        #pragma unroll
        for (int off = 4; off > 0; off >>= 1)
            mm = fmaxf(mm, __shfl_xor_sync(0xffffffffu, mm, off));
        if (tid == 0) red[32] = mm;
    }
    __syncthreads();
    float gmax = red[32];
    float e = expf(v - gmax);
    float ssum = e;
    #pragma unroll
    for (int off = 16; off > 0; off >>= 1)
        ssum += __shfl_xor_sync(0xffffffffu, ssum, off);
    if (l == 0) red[8 + w] = ssum;
    __syncthreads();
    if (tid < 32) {
        float s2 = (tid < 8) ? red[8 + tid] : 0.0f;
        #pragma unroll
        for (int off = 4; off > 0; off >>= 1)
            s2 += __shfl_xor_sync(0xffffffffu, s2, off);
        if (tid == 0) red[33] = 1.0f / s2;
    }
    __syncthreads();
    sp[tid] = e * red[33];
    __syncthreads();

    // phase 4: value = sum_t p[t] * o_enc[b,t,:]
    float4 a = make_float4(0.f, 0.f, 0.f, 0.f);
    const int col = tid << 2;
    #pragma unroll 4
    for (int t = 0; t < TE; ++t) {
        float p = sp[t];
        float4 o4 = *reinterpret_cast<const float4*>(ob + t * HH + col);
        a.x = fmaf(p, o4.x, a.x);
        a.y = fmaf(p, o4.y, a.y);
        a.z = fmaf(p, o4.z, a.z);
        a.w = fmaf(p, o4.w, a.w);
    }
    *reinterpret_cast<float4*>(&g_value[b * HH + col]) = a;
}

// ---------------- launcher ----------------------------------------------------------
extern "C" void kernel_launch(void* const* d_in, const int* in_sizes, int n_in,
                              void* d_out, int out_size)
{
    const float* x      = (const float*)d_in[0];
    const float* o_enc  = (const float*)d_in[1];
    const float* h_enc  = (const float*)d_in[2];
    const float* Wfeed  = (const float*)d_in[3];
    const float* bfeed  = (const float*)d_in[4];
    const float* Wx     = (const float*)d_in[5];
    const float* Wh     = (const float*)d_in[6];
    const float* bxi    = (const float*)d_in[7];
    const float* bhr    = (const float*)d_in[8];
    const float* Watt   = (const float*)d_in[9];
    const float* batt   = (const float*)d_in[10];
    float* out = (float*)d_out;

    init64<<<64, 1024>>>(h_enc);

    // precompute g_gxx[t] = x_t @ Wx[1024:] + bxi for all t (recurrence-independent)
    gstep<M_PRE><<<dim3(N3 / 16, TD), 256>>>(x, Wx + (size_t)HH * N3, bxi,
                                             nullptr, nullptr, nullptr, 0);

    for (int t = 0; t < TD; ++t) {
        gstep<M_FEED><<<HH / 16, 256>>>(nullptr, Wfeed, bfeed,
                                        nullptr, nullptr, nullptr, t);
        gstep<M_GXGH><<<dim3(N3 / 16, 2), 256>>>(nullptr, Wx, nullptr,
                                                 Wh, bhr, nullptr, t);
        attn64<<<BB, 256>>>(o_enc);
        gstep<M_HATT><<<HH / 16, 256>>>(nullptr, Watt, batt,
                                        nullptr, nullptr, out, t);
    }
}

// round 8
// speedup vs baseline: 3.0642x; 1.1644x over previous
#include <cuda_runtime.h>
#include <math.h>
#include <stdint.h>

#define BB 64
#define TD 128
#define TE 256
#define DX 1024
#define HH 1024
#define N3 3072

// ---------------- persistent state (device globals; no allocations) ----------------
__device__ float g_h[BB * HH];
__device__ float g_ifeed[BB * HH];
__device__ float g_feed[BB * HH];
__device__ float g_value[BB * HH];
__device__ float g_gxp[2][BB * N3];     // k-split partials of feed @ Wx[:1024]
__device__ float g_ghp[2][BB * N3];     // k-split partials of h @ Wh
__device__ float g_hattp[2][BB * HH];   // value/h halves of [value|h] @ Watt
__device__ float g_gxx[(size_t)TD * BB * N3];  // 96MB: x_t @ Wx[1024:] + bxi, all t

__global__ void init64(const float* __restrict__ h_enc) {
    int i = blockIdx.x * blockDim.x + threadIdx.x;
    if (i < BB * HH) { g_h[i] = h_enc[i]; g_ifeed[i] = 0.0f; }
}

__device__ __forceinline__ void ffma2(unsigned long long& a,
                                      unsigned long long x, unsigned long long y) {
    asm("fma.rn.f32x2 %0, %1, %2, %0;" : "+l"(a) : "l"(x), "l"(y));
}
__device__ __forceinline__ unsigned long long fadd2(unsigned long long x,
                                                    unsigned long long y) {
    unsigned long long d;
    asm("add.rn.f32x2 %0, %1, %2;" : "=l"(d) : "l"(x), "l"(y));
    return d;
}
__device__ __forceinline__ float lo2(unsigned long long v) {
    return __uint_as_float((unsigned)(v & 0xffffffffull));
}
__device__ __forceinline__ float hi2(unsigned long long v) {
    return __uint_as_float((unsigned)(v >> 32));
}

// ---------------- balanced FFMA2 GEMM core ------------------------------------------
// Block: 256 threads = 8 warps, C tile 64m x 32n. Each warp computes the FULL tile
// over k-quads {2w, 2w+1} of every 64-k chunk (8-way warp k-split), combined by a
// smem tree. Thread tile 8m x 8n with f32x2 k-pair accumulators.
// Per 4k per warp: 8 A LDS.128 + 8 W LDS.128 (conflict-free) + 128 FFMA2 -> 1:1
// crossbar:pipe balance. A staged row-major (m-permuted rows), W staged transposed.
// MODE 0 PRE : g_gxx[y] = x[:,y,:] @ Wx[1024:] + bxi       grid (96, TD)
// MODE 1 FEED: g_feed = tanh(g_ifeed @ Wfeed + bfeed)       grid (32)
// MODE 2 GXGH: y=gemm (0:gx from feed, 1:gh from h), z=k-half -> partials  grid (96,2,2)
// MODE 3 HATT: y=k-half (0:value, 1:h) -> g_hattp[y]        grid (32, 2)
template <int MODE>
__global__ __launch_bounds__(256, 1)
void gk(const float* __restrict__ pA, const float* __restrict__ pW,
        const float* __restrict__ pW2, const float* __restrict__ pBias)
{
    constexpr int K    = (MODE == 2) ? 512 : 1024;
    constexpr int NDIM = (MODE == 0 || MODE == 2) ? N3 : HH;
    constexpr int CH   = K / 64;

    __shared__ __align__(16) float smem[8448];   // sA 64x68 | sW 32x68 ; reused as red
    float* sA = smem;
    float* sW = smem + 64 * 68;

    const int tid  = threadIdx.x;
    const int w    = tid >> 5;
    const int lane = tid & 31;
    const int mg   = lane & 7;
    const int ng   = lane >> 3;
    const int n0   = blockIdx.x * 32;

    const float* A; size_t lda; int kA = 0;
    const float* W = pW; int wr0 = 0;
    const float* bias = pBias;
    float* C; size_t ldc;

    if (MODE == 0) {
        A = pA + (size_t)blockIdx.y * DX; lda = (size_t)TD * DX;
        C = g_gxx + (size_t)blockIdx.y * BB * N3; ldc = N3;
    } else if (MODE == 1) {
        A = g_ifeed; lda = HH;
        C = g_feed; ldc = HH;
    } else if (MODE == 2) {
        const int z = blockIdx.z;
        kA = z * 512; wr0 = z * 512;
        if (blockIdx.y == 0) { A = g_feed; W = pW;  C = g_gxp[z]; }
        else                 { A = g_h;    W = pW2; C = g_ghp[z]; }
        lda = HH; ldc = N3; bias = nullptr;
    } else {
        const int yy = blockIdx.y;
        A = yy ? g_h : g_value; lda = HH;
        wr0 = yy * HH;
        C = g_hattp[yy]; ldc = HH; bias = nullptr;
    }

    float4 ra[4];   // A staging regs
    float  rw[8];   // W staging regs (k-gathered)

    auto ldg = [&](int kc) {
        #pragma unroll
        for (int i = 0; i < 4; ++i) {
            int idx = i * 256 + tid;
            int m = idx >> 4, kq = idx & 15;
            ra[i] = *reinterpret_cast<const float4*>(
                A + (size_t)m * lda + kA + kc + kq * 4);
        }
        #pragma unroll
        for (int i = 0; i < 2; ++i) {
            int idx = i * 256 + tid;
            int n = idx & 31, kq = idx >> 5;
            #pragma unroll
            for (int kl = 0; kl < 4; ++kl)
                rw[i * 4 + kl] = W[(size_t)(wr0 + kc + kq * 4 + kl) * NDIM + n0 + n];
        }
    };
    auto sts = [&]() {
        #pragma unroll
        for (int i = 0; i < 4; ++i) {
            int idx = i * 256 + tid;
            int m = idx >> 4, kq = idx & 15;
            int r = (m & 7) * 8 + (m >> 3);           // permuted row
            *reinterpret_cast<float4*>(sA + r * 68 + kq * 4) = ra[i];
        }
        #pragma unroll
        for (int i = 0; i < 2; ++i) {
            int idx = i * 256 + tid;
            int n = idx & 31, kq = idx >> 5;
            *reinterpret_cast<float4*>(sW + n * 68 + kq * 4) =
                make_float4(rw[i * 4], rw[i * 4 + 1], rw[i * 4 + 2], rw[i * 4 + 3]);
        }
    };

    unsigned long long acc[8][8];
    #pragma unroll
    for (int j = 0; j < 8; ++j)
        #pragma unroll
        for (int jn = 0; jn < 8; ++jn) acc[j][jn] = 0ull;

    ldg(0); sts(); __syncthreads();

    #pragma unroll 1
    for (int c = 0; c < CH; ++c) {
        if (c + 1 < CH) ldg((c + 1) * 64);
        #pragma unroll
        for (int q = 0; q < 2; ++q) {
            const int kq = w * 2 + q;
            ulonglong2 wv[8];
            #pragma unroll
            for (int jn = 0; jn < 8; ++jn)
                wv[jn] = *reinterpret_cast<const ulonglong2*>(
                    sW + (ng * 8 + jn) * 68 + kq * 4);
            #pragma unroll
            for (int jh = 0; jh < 4; ++jh) {
                ulonglong2 av[2];
                #pragma unroll
                for (int jj = 0; jj < 2; ++jj)
                    av[jj] = *reinterpret_cast<const ulonglong2*>(
                        sA + ((jh * 2 + jj) * 8 + mg) * 68 + kq * 4);
                #pragma unroll
                for (int jj = 0; jj < 2; ++jj)
                    #pragma unroll
                    for (int jn = 0; jn < 8; ++jn) {
                        ffma2(acc[jh * 2 + jj][jn], av[jj].x, wv[jn].x);
                        ffma2(acc[jh * 2 + jj][jn], av[jj].y, wv[jn].y);
                    }
            }
        }
        __syncthreads();
        if (c + 1 < CH) { sts(); __syncthreads(); }
    }

    // ---- 8-way warp k-split reduce through smem (3 levels, 2 jn-halves each) ----
    unsigned long long* red = reinterpret_cast<unsigned long long*>(smem);
    #pragma unroll 1
    for (int r = 4; r >= 1; r >>= 1) {
        #pragma unroll
        for (int h = 0; h < 2; ++h) {
            if (w >= r && w < 2 * r) {
                unsigned long long* d = red + (size_t)((w - r) * 32 + lane) * 33;
                #pragma unroll
                for (int j = 0; j < 8; ++j)
                    #pragma unroll
                    for (int jn = 0; jn < 4; ++jn) d[j * 4 + jn] = acc[j][h * 4 + jn];
            }
            __syncthreads();
            if (w < r) {
                const unsigned long long* s = red + (size_t)(w * 32 + lane) * 33;
                #pragma unroll
                for (int j = 0; j < 8; ++j)
                    #pragma unroll
                    for (int jn = 0; jn < 4; ++jn)
                        acc[j][h * 4 + jn] = fadd2(acc[j][h * 4 + jn], s[j * 4 + jn]);
            }
            __syncthreads();
        }
    }

    // ---- epilogue (warp 0 holds the whole 64x32 tile) ----
    if (w == 0) {
        #pragma unroll
        for (int j = 0; j < 8; ++j) {
            const int m = mg * 8 + j;
            float v[8];
            #pragma unroll
            for (int jn = 0; jn < 8; ++jn) {
                const int n = n0 + ng * 8 + jn;
                float x = lo2(acc[j][jn]) + hi2(acc[j][jn]);
                if (bias) x += bias[n];
                if (MODE == 1) x = tanhf(x);
                v[jn] = x;
            }
            float* cp = C + (size_t)m * ldc + n0 + ng * 8;
            *reinterpret_cast<float4*>(cp)     = make_float4(v[0], v[1], v[2], v[3]);
            *reinterpret_cast<float4*>(cp + 4) = make_float4(v[4], v[5], v[6], v[7]);
        }
    }
}

// ---------------- HATT combine: tanh(p0 + p1 + batt) -> out[:,t,:], g_ifeed ---------
__global__ void combine_hatt(float* __restrict__ out, const float* __restrict__ batt) {
    int idx = blockIdx.x * blockDim.x + threadIdx.x;   // 64*1024 total
    int m = idx >> 10, n = idx & 1023;
    float v = tanhf(g_hattp[0][idx] + g_hattp[1][idx] + batt[n]);
    out[(size_t)m * TD * HH + n] = v;
    g_ifeed[idx] = v;
}

// ---------------- fused GRU-gate + attention (one block per batch row) --------------
__global__ __launch_bounds__(256)
void attn64(const float* __restrict__ o_enc, const float* __restrict__ bhr, int t)
{
    __shared__ __align__(16) float sh[HH];
    __shared__ float sp[TE];
    __shared__ float red[40];

    const int b = blockIdx.x;
    const int tid = threadIdx.x;
    const int w = tid >> 5;
    const int l = tid & 31;

    const float* gxx = g_gxx + (size_t)t * BB * N3 + (size_t)b * N3;

    // phase 1: sum GEMM partials + GRU elementwise (reset_after=True)
    #pragma unroll
    for (int r = 0; r < 4; ++r) {
        int i = (r << 8) + tid;
        int i0 = b * N3 + i, i1 = i0 + HH, i2 = i0 + 2 * HH;
        float xz  = g_gxp[0][i0] + g_gxp[1][i0] + gxx[i];
        float xr  = g_gxp[0][i1] + g_gxp[1][i1] + gxx[HH + i];
        float xh  = g_gxp[0][i2] + g_gxp[1][i2] + gxx[2 * HH + i];
        float hz  = g_ghp[0][i0] + g_ghp[1][i0] + bhr[i];
        float hr  = g_ghp[0][i1] + g_ghp[1][i1] + bhr[HH + i];
        float hh2 = g_ghp[0][i2] + g_ghp[1][i2] + bhr[2 * HH + i];
        float hp  = g_h[b * HH + i];
        float z  = 1.0f / (1.0f + expf(-(xz + hz)));
        float rr = 1.0f / (1.0f + expf(-(xr + hr)));
        float hc = tanhf(xh + rr * hh2);
        float hn = z * hp + (1.0f - z) * hc;
        sh[i] = hn;
        g_h[b * HH + i] = hn;
    }
    __syncthreads();

    // phase 2: scores[t'] = h_new . o_enc[b,t',:]
    const float* ob = o_enc + (size_t)b * TE * HH;
    for (int tt = 0; tt < 32; ++tt) {
        int te = (w << 5) + tt;
        const float* orow = ob + te * HH;
        float s = 0.0f;
        #pragma unroll
        for (int jj = 0; jj < 8; ++jj) {
            int i = (jj << 7) + (l << 2);
            float4 o4 = *reinterpret_cast<const float4*>(orow + i);
            float4 h4 = *reinterpret_cast<const float4*>(sh + i);
            s += o4.x * h4.x + o4.y * h4.y + o4.z * h4.z + o4.w * h4.w;
        }
        #pragma unroll
        for (int off = 16; off > 0; off >>= 1)
            s += __shfl_xor_sync(0xffffffffu, s, off);
        if (l == 0) sp[te] = s;
    }
    __syncthreads();

    // phase 3: softmax over 256
    float v = sp[tid];
    float m = v;
    #pragma unroll
    for (int off = 16; off > 0; off >>= 1)
        m = fmaxf(m, __shfl_xor_sync(0xffffffffu, m, off));
    if (l == 0) red[w] = m;
    __syncthreads();
    if (tid < 32) {
        float mm = (tid < 8) ? red[tid] : -1e30f;
        #pragma unroll
        for (int off = 4; off > 0; off >>= 1)
            mm = fmaxf(mm, __shfl_xor_sync(0xffffffffu, mm, off));
        if (tid == 0) red[32] = mm;
    }
    __syncthreads();
    float gmax = red[32];
    float e = expf(v - gmax);
    float ssum = e;
    #pragma unroll
    for (int off = 16; off > 0; off >>= 1)
        ssum += __shfl_xor_sync(0xffffffffu, ssum, off);
    if (l == 0) red[8 + w] = ssum;
    __syncthreads();
    if (tid < 32) {
        float s2 = (tid < 8) ? red[8 + tid] : 0.0f;
        #pragma unroll
        for (int off = 4; off > 0; off >>= 1)
            s2 += __shfl_xor_sync(0xffffffffu, s2, off);
        if (tid == 0) red[33] = 1.0f / s2;
    }
    __syncthreads();
    sp[tid] = e * red[33];
    __syncthreads();

    // phase 4: value = sum_t' p[t'] * o_enc[b,t',:]
    float4 a = make_float4(0.f, 0.f, 0.f, 0.f);
    const int col = tid << 2;
    #pragma unroll 4
    for (int te = 0; te < TE; ++te) {
        float p = sp[te];
        float4 o4 = *reinterpret_cast<const float4*>(ob + te * HH + col);
        a.x = fmaf(p, o4.x, a.x);
        a.y = fmaf(p, o4.y, a.y);
        a.z = fmaf(p, o4.z, a.z);
        a.w = fmaf(p, o4.w, a.w);
    }
    *reinterpret_cast<float4*>(&g_value[b * HH + col]) = a;
}

// ---------------- launcher ----------------------------------------------------------
extern "C" void kernel_launch(void* const* d_in, const int* in_sizes, int n_in,
                              void* d_out, int out_size)
{
    const float* x      = (const float*)d_in[0];
    const float* o_enc  = (const float*)d_in[1];
    const float* h_enc  = (const float*)d_in[2];
    const float* Wfeed  = (const float*)d_in[3];
    const float* bfeed  = (const float*)d_in[4];
    const float* Wx     = (const float*)d_in[5];
    const float* Wh     = (const float*)d_in[6];
    const float* bxi    = (const float*)d_in[7];
    const float* bhr    = (const float*)d_in[8];
    const float* Watt   = (const float*)d_in[9];
    const float* batt   = (const float*)d_in[10];
    float* out = (float*)d_out;

    init64<<<64, 1024>>>(h_enc);

    // precompute g_gxx[t] = x_t @ Wx[1024:] + bxi (recurrence-independent)
    gk<0><<<dim3(96, TD), 256>>>(x, Wx + (size_t)HH * N3, nullptr, bxi);

    for (int t = 0; t < TD; ++t) {
        gk<1><<<32, 256>>>(nullptr, Wfeed, nullptr, bfeed);
        gk<2><<<dim3(96, 2, 2), 256>>>(nullptr, Wx, Wh, nullptr);
        attn64<<<BB, 256>>>(o_enc, bhr, t);
        gk<3><<<dim3(32, 2), 256>>>(nullptr, Watt, nullptr, nullptr);
        combine_hatt<<<128, 512>>>(out + (size_t)t * HH, batt);
    }
}

// round 9
// speedup vs baseline: 4.9087x; 1.6019x over previous
#include <cuda_runtime.h>
#include <math.h>
#include <stdint.h>

#define BB 64
#define TD 128
#define TE 256
#define DX 1024
#define HH 1024
#define N3 3072

// ---------------- persistent state (device globals; no allocations) ----------------
__device__ float g_h[BB * HH];
__device__ float g_ifeed[BB * HH];
__device__ float g_feed[BB * HH];
__device__ float g_value[BB * HH];
__device__ float g_fp[4][BB * HH];      // FEED k-split partials
__device__ float g_gxp[2][BB * N3];     // gx k-split partials
__device__ float g_ghp[2][BB * N3];     // gh k-split partials
__device__ float g_hattp[4][BB * HH];   // HATT partials (y*2+z)
__device__ float g_gxx[(size_t)TD * BB * N3];  // 96MB: x_t @ Wx[1024:] + bxi

__global__ void init64(const float* __restrict__ h_enc) {
    int i = blockIdx.x * blockDim.x + threadIdx.x;
    if (i < BB * HH) { g_h[i] = h_enc[i]; g_ifeed[i] = 0.0f; }
}

__device__ __forceinline__ void ffma2(unsigned long long& a,
                                      unsigned long long x, unsigned long long y) {
    asm("fma.rn.f32x2 %0, %1, %2, %0;" : "+l"(a) : "l"(x), "l"(y));
}
__device__ __forceinline__ unsigned long long fadd2(unsigned long long x,
                                                    unsigned long long y) {
    unsigned long long d;
    asm("add.rn.f32x2 %0, %1, %2;" : "=l"(d) : "l"(x), "l"(y));
    return d;
}
__device__ __forceinline__ float lo2(unsigned long long v) {
    return __uint_as_float((unsigned)(v & 0xffffffffull));
}
__device__ __forceinline__ float hi2(unsigned long long v) {
    return __uint_as_float((unsigned)(v >> 32));
}

// ---------------- occupancy-friendly FFMA2 GEMM core --------------------------------
// Block 256 thr = 2 k-halves (kh) x 128 threads. C tile 64m x 32n.
// Positions p=0..127: mg=p&15, ng=p>>4. Thread tile: m = mg+16*mi (mi<4),
// n = n0+ng+8*ni (ni<4); 16 f32x2 k-pair accumulators (32 regs).
// smem: A as float2 k-pairs sA2[kp][m^kp] (XOR-swizzled), W as float2 pairs sW2[kp][n].
// Reads fully conflict-free (16 distinct m x 2-way bcast / 2 distinct n x 16-way bcast).
// Double-buffered 32-k chunks, ONE __syncthreads per chunk. 2-way k-split combined
// via one smem roundtrip; all 128 kh=0 threads run the epilogue.
// MODE 0 PRE : g_gxx[y] = x[:,y,:] @ Wx[1024:] + bxi     grid (96, TD)
// MODE 1 FEED: g_fp[y]  = ifeed[:, y*256:] @ Wfeed[y*256:,:]   grid (32, 4)
// MODE 2 GXGH: y: 0 gx (A=feed,W=Wx) / 1 gh (A=h,W=Wh); z: k-half  grid (96,2,2)
// MODE 3 HATT: y: A half (value/h); z: k-quarter -> g_hattp[y*2+z] grid (32,2,2)
template <int MODE>
__global__ __launch_bounds__(256, 2)
void gk2(const float* __restrict__ pA, const float* __restrict__ pW,
         const float* __restrict__ pW2, const float* __restrict__ pBias)
{
    constexpr int KW   = (MODE == 0) ? 1024 : (MODE == 1) ? 256 : 512;
    constexpr int KH   = KW / 2;
    constexpr int CH   = KH / 32;
    constexpr int NDIM = (MODE == 0 || MODE == 2) ? N3 : HH;

    __shared__ __align__(16) float2 sA2[2][2][16 * 64];   // 32KB
    __shared__ __align__(16) float2 sW2[2][2][16 * 32];   // 16KB

    const int tid = threadIdx.x;
    const int kh  = tid >> 7;
    const int p   = tid & 127;
    const int mg  = p & 15;
    const int ng  = p >> 4;
    const int n0  = blockIdx.x * 32;

    const float* A; size_t lda = HH;
    const float* W = pW;
    int kA = 0, kW = 0;
    float* C; size_t ldc;

    if (MODE == 0) {
        A = pA + (size_t)blockIdx.y * DX; lda = (size_t)TD * DX;
        C = g_gxx + (size_t)blockIdx.y * BB * N3; ldc = N3;
    } else if (MODE == 1) {
        const int z = blockIdx.y;
        A = g_ifeed; kA = kW = z * 256;
        C = g_fp[z]; ldc = HH;
    } else if (MODE == 2) {
        const int z = blockIdx.z;
        kA = kW = z * 512;
        if (blockIdx.y == 0) { A = g_feed; W = pW;  C = g_gxp[z]; }
        else                 { A = g_h;    W = pW2; C = g_ghp[z]; }
        ldc = N3;
    } else {
        const int y = blockIdx.y, z = blockIdx.z;
        A = y ? g_h : g_value;
        kA = z * 512; kW = y * HH + z * 512;
        C = g_hattp[y * 2 + z]; ldc = HH;
    }

    const int kbA = kA + kh * KH;
    const int kbW = kW + kh * KH;

    float4 ra[4];
    float2 rw[4];

    auto ldg = [&](int c) {
        const int kc = kbA + c * 32;
        #pragma unroll
        for (int i = 0; i < 4; ++i) {
            int idx = i * 128 + p;
            int m = idx >> 3, kq = idx & 7;
            ra[i] = *reinterpret_cast<const float4*>(A + (size_t)m * lda + kc + kq * 4);
        }
        const int kw = kbW + c * 32;
        #pragma unroll
        for (int i = 0; i < 4; ++i) {
            int idx = i * 128 + p;
            int n = idx & 31, kp = idx >> 5;
            rw[i].x = W[(size_t)(kw + 2 * kp)     * NDIM + n0 + n];
            rw[i].y = W[(size_t)(kw + 2 * kp + 1) * NDIM + n0 + n];
        }
    };
    auto sts = [&](int b) {
        float2* sa = sA2[kh][b];
        float2* sw = sW2[kh][b];
        #pragma unroll
        for (int i = 0; i < 4; ++i) {
            int idx = i * 128 + p;
            int m = idx >> 3, kq = idx & 7;
            int kp0 = 2 * kq, kp1 = 2 * kq + 1;
            sa[kp0 * 64 + (m ^ kp0)] = make_float2(ra[i].x, ra[i].y);
            sa[kp1 * 64 + (m ^ kp1)] = make_float2(ra[i].z, ra[i].w);
        }
        #pragma unroll
        for (int i = 0; i < 4; ++i) {
            int idx = i * 128 + p;
            int n = idx & 31, kp = idx >> 5;
            sw[kp * 32 + n] = rw[i];
        }
    };

    unsigned long long acc[4][4];
    #pragma unroll
    for (int mi = 0; mi < 4; ++mi)
        #pragma unroll
        for (int ni = 0; ni < 4; ++ni) acc[mi][ni] = 0ull;

    ldg(0); sts(0); __syncthreads();

    #pragma unroll 1
    for (int c = 0; c < CH; ++c) {
        if (c + 1 < CH) ldg(c + 1);
        const float2* sa = sA2[kh][c & 1];
        const float2* sw = sW2[kh][c & 1];
        #pragma unroll
        for (int kp = 0; kp < 16; ++kp) {
            const int mgx = mg ^ kp;            // kp literal -> folds to LOP3
            unsigned long long av[4], wv[4];
            #pragma unroll
            for (int mi = 0; mi < 4; ++mi)
                av[mi] = *reinterpret_cast<const unsigned long long*>(
                    &sa[kp * 64 + mgx + 16 * mi]);
            #pragma unroll
            for (int ni = 0; ni < 4; ++ni)
                wv[ni] = *reinterpret_cast<const unsigned long long*>(
                    &sw[kp * 32 + ng + 8 * ni]);
            #pragma unroll
            for (int mi = 0; mi < 4; ++mi)
                #pragma unroll
                for (int ni = 0; ni < 4; ++ni)
                    ffma2(acc[mi][ni], av[mi], wv[ni]);
        }
        if (c + 1 < CH) sts((c + 1) & 1);
        __syncthreads();
    }

    // ---- combine 2 k-halves: one smem roundtrip (staggered rows, degree-2) ----
    unsigned long long* red = reinterpret_cast<unsigned long long*>(&sA2[0][0][0]);
    if (kh == 1) {
        unsigned long long* d = red + (size_t)p * 17;
        #pragma unroll
        for (int mi = 0; mi < 4; ++mi)
            #pragma unroll
            for (int ni = 0; ni < 4; ++ni) d[mi * 4 + ni] = acc[mi][ni];
    }
    __syncthreads();
    if (kh == 0) {
        const unsigned long long* s = red + (size_t)p * 17;
        #pragma unroll
        for (int mi = 0; mi < 4; ++mi) {
            #pragma unroll
            for (int ni = 0; ni < 4; ++ni) {
                unsigned long long t = fadd2(acc[mi][ni], s[mi * 4 + ni]);
                float v = lo2(t) + hi2(t);
                const int m = mg + 16 * mi;
                const int n = n0 + ng + 8 * ni;
                if (MODE == 0) v += pBias[n];
                C[(size_t)m * ldc + n] = v;
            }
        }
    }
}

// ---------------- FEED combine: g_feed = tanh(sum fp + bfeed) -----------------------
__global__ void feedcomb(const float* __restrict__ bfeed) {
    int idx = blockIdx.x * blockDim.x + threadIdx.x;   // 64*1024
    int n = idx & 1023;
    g_feed[idx] = tanhf(g_fp[0][idx] + g_fp[1][idx] + g_fp[2][idx] + g_fp[3][idx]
                        + bfeed[n]);
}

// ---------------- HATT combine: tanh(sum hp + batt) -> out[:,t,:], g_ifeed ----------
__global__ void combine_hatt(float* __restrict__ out, const float* __restrict__ batt) {
    int idx = blockIdx.x * blockDim.x + threadIdx.x;   // 64*1024
    int m = idx >> 10, n = idx & 1023;
    float v = tanhf(g_hattp[0][idx] + g_hattp[1][idx] + g_hattp[2][idx]
                    + g_hattp[3][idx] + batt[n]);
    out[(size_t)m * TD * HH + n] = v;
    g_ifeed[idx] = v;
}

// ---------------- fused GRU-gate + attention (one block per batch row) --------------
__global__ __launch_bounds__(512)
void attn64(const float* __restrict__ o_enc, const float* __restrict__ bhr, int t)
{
    __shared__ __align__(16) float sh[HH];
    __shared__ float sp[TE];
    __shared__ float red[40];

    const int b = blockIdx.x;
    const int tid = threadIdx.x;
    const int w = tid >> 5;
    const int l = tid & 31;

    const float* gxx = g_gxx + (size_t)t * BB * N3 + (size_t)b * N3;

    // phase 1: sum GEMM partials + GRU elementwise (reset_after=True)
    #pragma unroll
    for (int r = 0; r < 2; ++r) {
        int i = (r << 9) + tid;
        int i0 = b * N3 + i, i1 = i0 + HH, i2 = i0 + 2 * HH;
        float xz  = g_gxp[0][i0] + g_gxp[1][i0] + gxx[i];
        float xr  = g_gxp[0][i1] + g_gxp[1][i1] + gxx[HH + i];
        float xh  = g_gxp[0][i2] + g_gxp[1][i2] + gxx[2 * HH + i];
        float hz  = g_ghp[0][i0] + g_ghp[1][i0] + bhr[i];
        float hr  = g_ghp[0][i1] + g_ghp[1][i1] + bhr[HH + i];
        float hh2 = g_ghp[0][i2] + g_ghp[1][i2] + bhr[2 * HH + i];
        float hp  = g_h[b * HH + i];
        float z  = 1.0f / (1.0f + expf(-(xz + hz)));
        float rr = 1.0f / (1.0f + expf(-(xr + hr)));
        float hc = tanhf(xh + rr * hh2);
        float hn = z * hp + (1.0f - z) * hc;
        sh[i] = hn;
        g_h[b * HH + i] = hn;
    }
    __syncthreads();

    // phase 2: scores (16 warps x 16 rows)
    const float* ob = o_enc + (size_t)b * TE * HH;
    #pragma unroll 1
    for (int tt = 0; tt < 16; ++tt) {
        int te = (w << 4) + tt;
        const float* orow = ob + te * HH;
        float s = 0.0f;
        #pragma unroll
        for (int jj = 0; jj < 8; ++jj) {
            int i = (jj << 7) + (l << 2);
            float4 o4 = *reinterpret_cast<const float4*>(orow + i);
            float4 h4 = *reinterpret_cast<const float4*>(sh + i);
            s += o4.x * h4.x + o4.y * h4.y + o4.z * h4.z + o4.w * h4.w;
        }
        #pragma unroll
        for (int off = 16; off > 0; off >>= 1)
            s += __shfl_xor_sync(0xffffffffu, s, off);
        if (l == 0) sp[te] = s;
    }
    __syncthreads();

    // phase 3: softmax over 256 (first 256 threads)
    float v = 0.0f, e = 0.0f;
    if (tid < 256) {
        v = sp[tid];
        float m = v;
        #pragma unroll
        for (int off = 16; off > 0; off >>= 1)
            m = fmaxf(m, __shfl_xor_sync(0xffffffffu, m, off));
        if (l == 0) red[w] = m;
    }
    __syncthreads();
    if (tid < 32) {
        float mm = (tid < 8) ? red[tid] : -1e30f;
        #pragma unroll
        for (int off = 4; off > 0; off >>= 1)
            mm = fmaxf(mm, __shfl_xor_sync(0xffffffffu, mm, off));
        if (tid == 0) red[32] = mm;
    }
    __syncthreads();
    if (tid < 256) {
        e = expf(v - red[32]);
        float ssum = e;
        #pragma unroll
        for (int off = 16; off > 0; off >>= 1)
            ssum += __shfl_xor_sync(0xffffffffu, ssum, off);
        if (l == 0) red[8 + w] = ssum;
    }
    __syncthreads();
    if (tid < 32) {
        float s2 = (tid < 8) ? red[8 + tid] : 0.0f;
        #pragma unroll
        for (int off = 4; off > 0; off >>= 1)
            s2 += __shfl_xor_sync(0xffffffffu, s2, off);
        if (tid == 0) red[33] = 1.0f / s2;
    }
    __syncthreads();
    if (tid < 256) sp[tid] = e * red[33];
    __syncthreads();

    // phase 4: value = sum_te p[te] * o_enc[b,te,:]  (float2, 512 thr x 2 cols)
    float2 a = make_float2(0.f, 0.f);
    const int col = tid << 1;
    #pragma unroll 4
    for (int te = 0; te < TE; ++te) {
        float pp = sp[te];
        float2 o2 = *reinterpret_cast<const float2*>(ob + te * HH + col);
        a.x = fmaf(pp, o2.x, a.x);
        a.y = fmaf(pp, o2.y, a.y);
    }
    *reinterpret_cast<float2*>(&g_value[b * HH + col]) = a;
}

// ---------------- launcher ----------------------------------------------------------
extern "C" void kernel_launch(void* const* d_in, const int* in_sizes, int n_in,
                              void* d_out, int out_size)
{
    const float* x      = (const float*)d_in[0];
    const float* o_enc  = (const float*)d_in[1];
    const float* h_enc  = (const float*)d_in[2];
    const float* Wfeed  = (const float*)d_in[3];
    const float* bfeed  = (const float*)d_in[4];
    const float* Wx     = (const float*)d_in[5];
    const float* Wh     = (const float*)d_in[6];
    const float* bxi    = (const float*)d_in[7];
    const float* bhr    = (const float*)d_in[8];
    const float* Watt   = (const float*)d_in[9];
    const float* batt   = (const float*)d_in[10];
    float* out = (float*)d_out;

    init64<<<64, 1024>>>(h_enc);

    // precompute g_gxx[t] = x_t @ Wx[1024:] + bxi (recurrence-independent)
    gk2<0><<<dim3(96, TD), 256>>>(x, Wx + (size_t)HH * N3, nullptr, bxi);

    for (int t = 0; t < TD; ++t) {
        gk2<1><<<dim3(32, 4), 256>>>(nullptr, Wfeed, nullptr, nullptr);
        feedcomb<<<128, 512>>>(bfeed);
        gk2<2><<<dim3(96, 2, 2), 256>>>(nullptr, Wx, Wh, nullptr);
        attn64<<<BB, 512>>>(o_enc, bhr, t);
        gk2<3><<<dim3(32, 2, 2), 256>>>(nullptr, Watt, nullptr, nullptr);
        combine_hatt<<<128, 512>>>(out + (size_t)t * HH, batt);
    }
}

// round 10
// speedup vs baseline: 5.8351x; 1.1887x over previous
#include <cuda_runtime.h>
#include <math.h>
#include <stdint.h>

#define BB 64
#define TD 128
#define TE 256
#define DX 1024
#define HH 1024
#define N3 3072

// ---------------- persistent state (device globals; no allocations) ----------------
__device__ float g_h[2][BB * HH];       // ping-pong GRU state (parity by step)
__device__ float g_ifeed[BB * HH];
__device__ float g_feed[BB * HH];
__device__ float g_value[BB * HH];
__device__ float g_fp[4][BB * HH];      // FEED k-split partials
__device__ float g_gxp[4][BB * N3];     // gx k-split partials
__device__ float g_ghp[4][BB * N3];     // gh k-split partials
__device__ float g_hattp[8][BB * HH];   // HATT partials (y*4+z)
__device__ float g_attv[4][BB * HH];    // attention value partials
__device__ float g_attm[4][BB];         // attention local max
__device__ float g_atts[4][BB];         // attention local expsum
__device__ float g_gxx[(size_t)TD * BB * N3];  // 96MB: x_t @ Wx[1024:] + bxi

__global__ void init64(const float* __restrict__ h_enc) {
    int i = blockIdx.x * blockDim.x + threadIdx.x;
    if (i < BB * HH) { g_h[0][i] = h_enc[i]; g_ifeed[i] = 0.0f; }
}

__device__ __forceinline__ void ffma2(unsigned long long& a,
                                      unsigned long long x, unsigned long long y) {
    asm("fma.rn.f32x2 %0, %1, %2, %0;" : "+l"(a) : "l"(x), "l"(y));
}
__device__ __forceinline__ unsigned long long fadd2(unsigned long long x,
                                                    unsigned long long y) {
    unsigned long long d;
    asm("add.rn.f32x2 %0, %1, %2;" : "=l"(d) : "l"(x), "l"(y));
    return d;
}
__device__ __forceinline__ float lo2(unsigned long long v) {
    return __uint_as_float((unsigned)(v & 0xffffffffull));
}
__device__ __forceinline__ float hi2(unsigned long long v) {
    return __uint_as_float((unsigned)(v >> 32));
}

// ---------------- FFMA2 GEMM core (same balanced inner loop as R8) ------------------
// Block 256 thr = 2 in-block k-halves (kh) x 128 positions. C tile 64m x 32n.
// Thread tile 4m x 4n strided; 16 f32x2 k-pair accumulators.
// MODE 0 PRE : g_gxx[y] = x[:,y,:] @ Wx[1024:] + bxi          grid (96, TD)
// MODE 1 FEED: g_fp[y]  = ifeed[:, y*256:] @ Wfeed[slice]     grid (32, 4)
// MODE 2 GXGH: y 0/1 gx/gh; z k-quarter -> g_gxp/ghp[z]       grid (96, 2, 4)
// MODE 3 HATT: y value/h half; z k-quarter -> g_hattp[y*4+z]  grid (32, 2, 4)
template <int MODE>
__global__ __launch_bounds__(256, 2)
void gk2(const float* __restrict__ pA, const float* __restrict__ pW,
         const float* __restrict__ pW2, const float* __restrict__ pBias, int hsel)
{
    constexpr int KW   = (MODE == 0) ? 1024 : 256;
    constexpr int KH   = KW / 2;
    constexpr int CH   = KH / 32;
    constexpr int NDIM = (MODE == 0 || MODE == 2) ? N3 : HH;

    __shared__ __align__(16) float2 sA2[2][2][16 * 64];   // 32KB
    __shared__ __align__(16) float2 sW2[2][2][16 * 32];   // 16KB

    const int tid = threadIdx.x;
    const int kh  = tid >> 7;
    const int p   = tid & 127;
    const int mg  = p & 15;
    const int ng  = p >> 4;
    const int n0  = blockIdx.x * 32;

    const float* A; size_t lda = HH;
    const float* W = pW;
    int kA = 0, kW2 = 0;
    float* C; size_t ldc;

    if (MODE == 0) {
        A = pA + (size_t)blockIdx.y * DX; lda = (size_t)TD * DX;
        C = g_gxx + (size_t)blockIdx.y * BB * N3; ldc = N3;
    } else if (MODE == 1) {
        const int z = blockIdx.y;
        A = g_ifeed; kA = kW2 = z * 256;
        C = g_fp[z]; ldc = HH;
    } else if (MODE == 2) {
        const int z = blockIdx.z;
        kA = kW2 = z * 256;
        if (blockIdx.y == 0) { A = g_feed;     W = pW;  C = g_gxp[z]; }
        else                 { A = g_h[hsel];  W = pW2; C = g_ghp[z]; }
        ldc = N3;
    } else {
        const int y = blockIdx.y, z = blockIdx.z;
        A = y ? g_h[hsel] : g_value;
        kA = z * 256; kW2 = y * HH + z * 256;
        C = g_hattp[y * 4 + z]; ldc = HH;
    }

    const int kbA = kA + kh * KH;
    const int kbW = kW2 + kh * KH;

    float4 ra[4];
    float2 rw[4];

    auto ldg = [&](int c) {
        const int kc = kbA + c * 32;
        #pragma unroll
        for (int i = 0; i < 4; ++i) {
            int idx = i * 128 + p;
            int m = idx >> 3, kq = idx & 7;
            ra[i] = *reinterpret_cast<const float4*>(A + (size_t)m * lda + kc + kq * 4);
        }
        const int kw = kbW + c * 32;
        #pragma unroll
        for (int i = 0; i < 4; ++i) {
            int idx = i * 128 + p;
            int n = idx & 31, kp = idx >> 5;
            rw[i].x = W[(size_t)(kw + 2 * kp)     * NDIM + n0 + n];
            rw[i].y = W[(size_t)(kw + 2 * kp + 1) * NDIM + n0 + n];
        }
    };
    auto sts = [&](int b) {
        float2* sa = sA2[kh][b];
        float2* sw = sW2[kh][b];
        #pragma unroll
        for (int i = 0; i < 4; ++i) {
            int idx = i * 128 + p;
            int m = idx >> 3, kq = idx & 7;
            int kp0 = 2 * kq, kp1 = 2 * kq + 1;
            sa[kp0 * 64 + (m ^ kp0)] = make_float2(ra[i].x, ra[i].y);
            sa[kp1 * 64 + (m ^ kp1)] = make_float2(ra[i].z, ra[i].w);
        }
        #pragma unroll
        for (int i = 0; i < 4; ++i) {
            int idx = i * 128 + p;
            int n = idx & 31, kp = idx >> 5;
            sw[kp * 32 + n] = rw[i];
        }
    };

    unsigned long long acc[4][4];
    #pragma unroll
    for (int mi = 0; mi < 4; ++mi)
        #pragma unroll
        for (int ni = 0; ni < 4; ++ni) acc[mi][ni] = 0ull;

    ldg(0); sts(0); __syncthreads();

    #pragma unroll 1
    for (int c = 0; c < CH; ++c) {
        if (c + 1 < CH) ldg(c + 1);
        const float2* sa = sA2[kh][c & 1];
        const float2* sw = sW2[kh][c & 1];
        #pragma unroll
        for (int kp = 0; kp < 16; ++kp) {
            const int mgx = mg ^ kp;
            unsigned long long av[4], wv[4];
            #pragma unroll
            for (int mi = 0; mi < 4; ++mi)
                av[mi] = *reinterpret_cast<const unsigned long long*>(
                    &sa[kp * 64 + mgx + 16 * mi]);
            #pragma unroll
            for (int ni = 0; ni < 4; ++ni)
                wv[ni] = *reinterpret_cast<const unsigned long long*>(
                    &sw[kp * 32 + ng + 8 * ni]);
            #pragma unroll
            for (int mi = 0; mi < 4; ++mi)
                #pragma unroll
                for (int ni = 0; ni < 4; ++ni)
                    ffma2(acc[mi][ni], av[mi], wv[ni]);
        }
        if (c + 1 < CH) sts((c + 1) & 1);
        __syncthreads();
    }

    // combine 2 in-block k-halves: one smem roundtrip
    unsigned long long* red = reinterpret_cast<unsigned long long*>(&sA2[0][0][0]);
    if (kh == 1) {
        unsigned long long* d = red + (size_t)p * 17;
        #pragma unroll
        for (int mi = 0; mi < 4; ++mi)
            #pragma unroll
            for (int ni = 0; ni < 4; ++ni) d[mi * 4 + ni] = acc[mi][ni];
    }
    __syncthreads();
    if (kh == 0) {
        const unsigned long long* s = red + (size_t)p * 17;
        #pragma unroll
        for (int mi = 0; mi < 4; ++mi) {
            #pragma unroll
            for (int ni = 0; ni < 4; ++ni) {
                unsigned long long tv = fadd2(acc[mi][ni], s[mi * 4 + ni]);
                float v = lo2(tv) + hi2(tv);
                const int m = mg + 16 * mi;
                const int n = n0 + ng + 8 * ni;
                if (MODE == 0) v += pBias[n];
                C[(size_t)m * ldc + n] = v;
            }
        }
    }
}

// ---------------- FEED combine ------------------------------------------------------
__global__ void feedcomb(const float* __restrict__ bfeed) {
    int idx = blockIdx.x * blockDim.x + threadIdx.x;
    int n = idx & 1023;
    g_feed[idx] = tanhf(g_fp[0][idx] + g_fp[1][idx] + g_fp[2][idx] + g_fp[3][idx]
                        + bfeed[n]);
}

// ---------------- HATT combine ------------------------------------------------------
__global__ void combine_hatt(float* __restrict__ out, const float* __restrict__ batt) {
    int idx = blockIdx.x * blockDim.x + threadIdx.x;
    int m = idx >> 10, n = idx & 1023;
    float v = g_hattp[0][idx] + g_hattp[1][idx] + g_hattp[2][idx] + g_hattp[3][idx]
            + g_hattp[4][idx] + g_hattp[5][idx] + g_hattp[6][idx] + g_hattp[7][idx]
            + batt[n];
    v = tanhf(v);
    out[(size_t)m * TD * HH + n] = v;
    g_ifeed[idx] = v;
}

// ---------------- partial attention: GRU gates + local softmax over 64 te rows ------
// grid (64 b, 4 z). Each block: redundant GRU -> h_new (z==0 writes next h buffer),
// scores for te in [z*64, z*64+64), local max/expsum, unnormalized value partial.
__global__ __launch_bounds__(512)
void attnp(const float* __restrict__ o_enc, const float* __restrict__ bhr, int t)
{
    __shared__ __align__(16) float sh[HH];
    __shared__ float sp[64];
    __shared__ float red[8];

    const int b = blockIdx.x;
    const int z = blockIdx.y;
    const int tid = threadIdx.x;
    const int w = tid >> 5;
    const int l = tid & 31;
    const int hsel = t & 1;

    const float* gxx = g_gxx + (size_t)t * BB * N3 + (size_t)b * N3;
    const float* hcur = g_h[hsel];
    float* hnxt = g_h[hsel ^ 1];

    // phase 1: sum GEMM partials + GRU elementwise (reset_after=True)
    #pragma unroll
    for (int r = 0; r < 2; ++r) {
        int i = (r << 9) + tid;
        int i0 = b * N3 + i, i1 = i0 + HH, i2 = i0 + 2 * HH;
        float xz  = g_gxp[0][i0] + g_gxp[1][i0] + g_gxp[2][i0] + g_gxp[3][i0] + gxx[i];
        float xr  = g_gxp[0][i1] + g_gxp[1][i1] + g_gxp[2][i1] + g_gxp[3][i1] + gxx[HH + i];
        float xh  = g_gxp[0][i2] + g_gxp[1][i2] + g_gxp[2][i2] + g_gxp[3][i2] + gxx[2 * HH + i];
        float hz  = g_ghp[0][i0] + g_ghp[1][i0] + g_ghp[2][i0] + g_ghp[3][i0] + bhr[i];
        float hr  = g_ghp[0][i1] + g_ghp[1][i1] + g_ghp[2][i1] + g_ghp[3][i1] + bhr[HH + i];
        float hh2 = g_ghp[0][i2] + g_ghp[1][i2] + g_ghp[2][i2] + g_ghp[3][i2] + bhr[2 * HH + i];
        float hp  = hcur[b * HH + i];
        float zz = 1.0f / (1.0f + expf(-(xz + hz)));
        float rr = 1.0f / (1.0f + expf(-(xr + hr)));
        float hc = tanhf(xh + rr * hh2);
        float hn = zz * hp + (1.0f - zz) * hc;
        sh[i] = hn;
        if (z == 0) hnxt[b * HH + i] = hn;
    }
    __syncthreads();

    // phase 2: scores for 64 rows (16 warps x 4 rows)
    const float* ob = o_enc + (size_t)b * TE * HH;
    #pragma unroll
    for (int tt = 0; tt < 4; ++tt) {
        int tl = (w << 2) + tt;
        const float* orow = ob + (z * 64 + tl) * HH;
        float s = 0.0f;
        #pragma unroll
        for (int jj = 0; jj < 8; ++jj) {
            int i = (jj << 7) + (l << 2);
            float4 o4 = *reinterpret_cast<const float4*>(orow + i);
            float4 h4 = *reinterpret_cast<const float4*>(sh + i);
            s += o4.x * h4.x + o4.y * h4.y + o4.z * h4.z + o4.w * h4.w;
        }
        #pragma unroll
        for (int off = 16; off > 0; off >>= 1)
            s += __shfl_xor_sync(0xffffffffu, s, off);
        if (l == 0) sp[tl] = s;
    }
    __syncthreads();

    // phase 3: local softmax stats over 64 scores (warps 0-1)
    float v = 0.0f;
    if (tid < 64) {
        v = sp[tid];
        float m = v;
        #pragma unroll
        for (int off = 16; off > 0; off >>= 1)
            m = fmaxf(m, __shfl_xor_sync(0xffffffffu, m, off));
        if (l == 0) red[w] = m;
    }
    __syncthreads();
    const float M = fmaxf(red[0], red[1]);
    if (tid < 64) {
        float e = expf(v - M);
        float s = e;
        #pragma unroll
        for (int off = 16; off > 0; off >>= 1)
            s += __shfl_xor_sync(0xffffffffu, s, off);
        if (l == 0) red[2 + w] = s;
        sp[tid] = e;
    }
    __syncthreads();
    if (tid == 0) { g_attm[z][b] = M; g_atts[z][b] = red[2] + red[3]; }

    // phase 4: unnormalized value partial (512 thr x 2 cols)
    float2 a = make_float2(0.f, 0.f);
    const int col = tid << 1;
    const float* obz = ob + z * 64 * HH;
    #pragma unroll 4
    for (int te = 0; te < 64; ++te) {
        float pp = sp[te];
        float2 o2 = *reinterpret_cast<const float2*>(obz + te * HH + col);
        a.x = fmaf(pp, o2.x, a.x);
        a.y = fmaf(pp, o2.y, a.y);
    }
    *reinterpret_cast<float2*>(&g_attv[z][b * HH + col]) = a;
}

// ---------------- attention combine: merge 4 partial softmaxes ----------------------
__global__ __launch_bounds__(512)
void attnc()
{
    const int b = blockIdx.x;
    const int tid = threadIdx.x;
    float m0 = g_attm[0][b], m1 = g_attm[1][b], m2 = g_attm[2][b], m3 = g_attm[3][b];
    float M = fmaxf(fmaxf(m0, m1), fmaxf(m2, m3));
    float c0 = expf(m0 - M), c1 = expf(m1 - M), c2 = expf(m2 - M), c3 = expf(m3 - M);
    float inv = 1.0f / (g_atts[0][b] * c0 + g_atts[1][b] * c1 +
                        g_atts[2][b] * c2 + g_atts[3][b] * c3);
    const int col = tid << 1;
    float2 v0 = *reinterpret_cast<const float2*>(&g_attv[0][b * HH + col]);
    float2 v1 = *reinterpret_cast<const float2*>(&g_attv[1][b * HH + col]);
    float2 v2 = *reinterpret_cast<const float2*>(&g_attv[2][b * HH + col]);
    float2 v3 = *reinterpret_cast<const float2*>(&g_attv[3][b * HH + col]);
    float2 r;
    r.x = (v0.x * c0 + v1.x * c1 + v2.x * c2 + v3.x * c3) * inv;
    r.y = (v0.y * c0 + v1.y * c1 + v2.y * c2 + v3.y * c3) * inv;
    *reinterpret_cast<float2*>(&g_value[b * HH + col]) = r;
}

// ---------------- launcher ----------------------------------------------------------
extern "C" void kernel_launch(void* const* d_in, const int* in_sizes, int n_in,
                              void* d_out, int out_size)
{
    const float* x      = (const float*)d_in[0];
    const float* o_enc  = (const float*)d_in[1];
    const float* h_enc  = (const float*)d_in[2];
    const float* Wfeed  = (const float*)d_in[3];
    const float* bfeed  = (const float*)d_in[4];
    const float* Wx     = (const float*)d_in[5];
    const float* Wh     = (const float*)d_in[6];
    const float* bxi    = (const float*)d_in[7];
    const float* bhr    = (const float*)d_in[8];
    const float* Watt   = (const float*)d_in[9];
    const float* batt   = (const float*)d_in[10];
    float* out = (float*)d_out;

    init64<<<64, 1024>>>(h_enc);

    // precompute g_gxx[t] = x_t @ Wx[1024:] + bxi (recurrence-independent)
    gk2<0><<<dim3(96, TD), 256>>>(x, Wx + (size_t)HH * N3, nullptr, bxi, 0);

    for (int t = 0; t < TD; ++t) {
        gk2<1><<<dim3(32, 4), 256>>>(nullptr, Wfeed, nullptr, nullptr, 0);
        feedcomb<<<128, 512>>>(bfeed);
        gk2<2><<<dim3(96, 2, 4), 256>>>(nullptr, Wx, Wh, nullptr, t & 1);
        attnp<<<dim3(BB, 4), 512>>>(o_enc, bhr, t);
        attnc<<<BB, 512>>>();
        gk2<3><<<dim3(32, 2, 4), 256>>>(nullptr, Watt, nullptr, nullptr, (t + 1) & 1);
        combine_hatt<<<128, 512>>>(out + (size_t)t * HH, batt);
    }
}